// round 1
// baseline (speedup 1.0000x reference)
#include <cuda_runtime.h>

// ---------------------------------------------------------------------------
// FeatureQuantizerEMA — VQ-VAE EMA vector quantizer
//   x:           [32, 256, 64, 64] fp32   (d_in[0])
//   embed:       [256, 1024] fp32         (d_in[1])
//   cluster_size:[1024] fp32              (d_in[2])
//   ema_embed:   [256, 1024] fp32         (d_in[3])
// Output (concatenated fp32):
//   out[33554432], loss[1], embed_idx[131072],
//   new_embed[262144], new_cluster_size[1024], new_ema_embed[262144]
// ---------------------------------------------------------------------------

#define N_TOK 131072
#define DEMB 256
#define KEMB 1024
#define HWSZ 4096
#define NBATCH 32

// scratch (no device allocation allowed -> __device__ globals)
__device__ float g_norms[KEMB];
__device__ int   g_idx[N_TOK];
__device__ float g_minval[N_TOK];
__device__ float g_refcount[KEMB];
__device__ float g_dw[DEMB * KEMB];
__device__ float g_smooth[KEMB];
__device__ float g_minsum;
__device__ float g_xsq;

// ---- packed f32x2 helpers (Blackwell FFMA2) --------------------------------
__device__ __forceinline__ unsigned long long pack2(float lo, float hi) {
    unsigned long long r;
    asm("mov.b64 %0, {%1, %2};" : "=l"(r) : "f"(lo), "f"(hi));
    return r;
}
__device__ __forceinline__ void unpack2(unsigned long long v, float& lo, float& hi) {
    asm("mov.b64 {%0, %1}, %2;" : "=f"(lo), "=f"(hi) : "l"(v));
}
__device__ __forceinline__ unsigned long long fma2(unsigned long long a,
                                                   unsigned long long b,
                                                   unsigned long long c) {
    unsigned long long d;
    asm("fma.rn.f32x2 %0, %1, %2, %3;" : "=l"(d) : "l"(a), "l"(b), "l"(c));
    return d;
}

// ---------------------------------------------------------------------------
__global__ void zero_kernel() {
    int i = blockIdx.x * blockDim.x + threadIdx.x;
    int stride = gridDim.x * blockDim.x;
    for (int j = i; j < DEMB * KEMB; j += stride) g_dw[j] = 0.0f;
    if (i < KEMB) g_refcount[i] = 0.0f;
    if (i == 0) { g_minsum = 0.0f; g_xsq = 0.0f; }
}

__global__ void norms_kernel(const float* __restrict__ embed) {
    int k = blockIdx.x * blockDim.x + threadIdx.x;
    if (k < KEMB) {
        float s = 0.0f;
        #pragma unroll 8
        for (int d = 0; d < DEMB; d++) {
            float v = embed[d * KEMB + k];
            s = fmaf(v, v, s);
        }
        g_norms[k] = s;
    }
}

// ---------------------------------------------------------------------------
// Fused distance GEMM + argmin.
// Block: 128 tokens x all 1024 codes, processed in 64-code chunks.
// Threads: 256 = 16(tx: code) x 16(ty: token). Each thread: 8 rows x 4 cols,
// rows paired into f32x2 lanes -> 16 FFMA2 per k-step.
// ---------------------------------------------------------------------------
__global__ __launch_bounds__(256) void argmin_kernel(const float* __restrict__ x,
                                                     const float* __restrict__ embed) {
    __shared__ float As[16][128];   // [d][token]
    __shared__ float Bs[16][64];    // [d][code]
    __shared__ float sN[KEMB];
    __shared__ float rv[128][16];
    __shared__ int   ri[128][16];

    const int tid = threadIdx.x;
    const int tx = tid & 15;
    const int ty = tid >> 4;
    const int row0 = ty * 8;

    const int n0 = blockIdx.x * 128;
    const int b = n0 >> 12;          // / 4096
    const int hw0 = n0 & 4095;
    const float* xb = x + (size_t)b * DEMB * HWSZ + hw0;

    for (int i = tid; i < KEMB; i += 256) sN[i] = g_norms[i];

    float bestv[8];
    int   besti[8];
    #pragma unroll
    for (int p = 0; p < 8; p++) { bestv[p] = 3.4e38f; besti[p] = 0; }

    for (int k0 = 0; k0 < KEMB; k0 += 64) {
        unsigned long long acc[4][4];
        #pragma unroll
        for (int p = 0; p < 4; p++)
            #pragma unroll
            for (int j = 0; j < 4; j++) acc[p][j] = 0ULL;

        for (int d0 = 0; d0 < DEMB; d0 += 16) {
            __syncthreads();
            // load A tile: 16 d x 128 tokens (coalesced, L2-resident on reload)
            {
                const int m = tid & 127;
                const int half = tid >> 7;
                #pragma unroll
                for (int pass = 0; pass < 8; pass++) {
                    int dd = half * 8 + pass;
                    As[dd][m] = xb[(size_t)(d0 + dd) * HWSZ + m];
                }
            }
            // load B tile: 16 d x 64 codes
            {
                const int j = tid & 63;
                const int q = tid >> 6;
                #pragma unroll
                for (int pass = 0; pass < 4; pass++) {
                    int dd = q + pass * 4;
                    Bs[dd][j] = embed[(d0 + dd) * KEMB + k0 + j];
                }
            }
            __syncthreads();

            #pragma unroll
            for (int kk = 0; kk < 16; kk++) {
                unsigned long long a2[4];
                #pragma unroll
                for (int p = 0; p < 4; p++) {
                    float2 av = *(const float2*)&As[kk][row0 + 2 * p];
                    a2[p] = pack2(av.x, av.y);
                }
                float4 bq = *(const float4*)&Bs[kk][tx * 4];
                unsigned long long b2[4];
                b2[0] = pack2(bq.x, bq.x);
                b2[1] = pack2(bq.y, bq.y);
                b2[2] = pack2(bq.z, bq.z);
                b2[3] = pack2(bq.w, bq.w);
                #pragma unroll
                for (int p = 0; p < 4; p++) {
                    #pragma unroll
                    for (int j = 0; j < 4; j++)
                        acc[p][j] = fma2(a2[p], b2[j], acc[p][j]);
                }
            }
        }

        // epilogue: score = |e_k|^2 - 2*dot, running argmin (k ascending)
        #pragma unroll
        for (int j = 0; j < 4; j++) {
            int k = k0 + tx * 4 + j;
            float nk = sN[k];
            #pragma unroll
            for (int p = 0; p < 4; p++) {
                float lo, hi;
                unpack2(acc[p][j], lo, hi);
                float s0 = fmaf(-2.0f, lo, nk);
                float s1 = fmaf(-2.0f, hi, nk);
                if (s0 < bestv[2 * p])     { bestv[2 * p] = s0;     besti[2 * p] = k; }
                if (s1 < bestv[2 * p + 1]) { bestv[2 * p + 1] = s1; besti[2 * p + 1] = k; }
            }
        }
    }

    // cross-thread reduction over the 16 tx-lanes sharing each token row
    #pragma unroll
    for (int p = 0; p < 8; p++) {
        rv[row0 + p][tx] = bestv[p];
        ri[row0 + p][tx] = besti[p];
    }
    __syncthreads();
    if (tid < 128) {
        float bv = rv[tid][0];
        int   bi = ri[tid][0];
        #pragma unroll
        for (int t = 1; t < 16; t++) {
            float v = rv[tid][t];
            int   ii = ri[tid][t];
            if (v < bv || (v == bv && ii < bi)) { bv = v; bi = ii; }
        }
        g_minval[n0 + tid] = bv;
        g_idx[n0 + tid] = bi;
    }
}

// ---------------------------------------------------------------------------
__global__ void stats_kernel(float* __restrict__ out_idx) {
    int n = blockIdx.x * 256 + threadIdx.x;
    int idx = g_idx[n];
    atomicAdd(&g_refcount[idx], 1.0f);
    out_idx[n] = (float)idx;

    float v = g_minval[n];
    #pragma unroll
    for (int o = 16; o > 0; o >>= 1) v += __shfl_down_sync(0xffffffffu, v, o);
    __shared__ float ws[8];
    if ((threadIdx.x & 31) == 0) ws[threadIdx.x >> 5] = v;
    __syncthreads();
    if (threadIdx.x == 0) {
        float s = 0.0f;
        #pragma unroll
        for (int w = 0; w < 8; w++) s += ws[w];
        atomicAdd(&g_minsum, s);
    }
}

__global__ void xsq_kernel(const float4* __restrict__ x4) {
    int i = blockIdx.x * blockDim.x + threadIdx.x;
    int stride = gridDim.x * blockDim.x;
    float s = 0.0f;
    for (int j = i; j < (N_TOK * DEMB) / 4; j += stride) {
        float4 v = x4[j];
        s = fmaf(v.x, v.x, s);
        s = fmaf(v.y, v.y, s);
        s = fmaf(v.z, v.z, s);
        s = fmaf(v.w, v.w, s);
    }
    #pragma unroll
    for (int o = 16; o > 0; o >>= 1) s += __shfl_down_sync(0xffffffffu, s, o);
    __shared__ float ws[8];
    if ((threadIdx.x & 31) == 0) ws[threadIdx.x >> 5] = s;
    __syncthreads();
    if (threadIdx.x == 0) {
        float t = 0.0f;
        #pragma unroll
        for (int w = 0; w < 8; w++) t += ws[w];
        atomicAdd(&g_xsq, t);
    }
}

// dw[d][k] += flat[n][d] for idx[n]==k  (scatter-add, coalesced x reads)
__global__ void dw_kernel(const float* __restrict__ x) {
    int n = blockIdx.x * 256 + threadIdx.x;
    int b = n >> 12;
    int hw = n & 4095;
    int idx = g_idx[n];
    const float* xb = x + (size_t)b * DEMB * HWSZ + hw;
    float* dwp = g_dw + idx;
    #pragma unroll 4
    for (int d = 0; d < DEMB; d++)
        atomicAdd(&dwp[d * KEMB], xb[(size_t)d * HWSZ]);
}

__global__ void cluster_kernel(const float* __restrict__ cs_in,
                               float* __restrict__ out_ncs,
                               float* __restrict__ out_loss) {
    int k = threadIdx.x;  // 1024 threads
    float ncs = cs_in[k] * 0.9f + 0.1f * g_refcount[k];
    out_ncs[k] = ncs;

    // block-wide sum of ncs
    float v = ncs;
    #pragma unroll
    for (int o = 16; o > 0; o >>= 1) v += __shfl_down_sync(0xffffffffu, v, o);
    __shared__ float ws[32];
    if ((k & 31) == 0) ws[k >> 5] = v;
    __syncthreads();
    __shared__ float s_n;
    if (k < 32) {
        float t = ws[k];
        #pragma unroll
        for (int o = 16; o > 0; o >>= 1) t += __shfl_down_sync(0xffffffffu, t, o);
        if (k == 0) s_n = t;
    }
    __syncthreads();
    float n = s_n;
    float smoothing = n * (ncs + 1e-5f) / (n + ncs * 1e-5f);
    g_smooth[k] = smoothing;
    if (k == 0)
        out_loss[0] = 0.25f * (g_minsum + g_xsq) / 33554432.0f;
}

__global__ void ema_kernel(const float* __restrict__ ema_in,
                           float* __restrict__ out_nee,
                           float* __restrict__ out_ne) {
    int i = blockIdx.x * blockDim.x + threadIdx.x;  // 262144
    float nee = ema_in[i] * 0.9f + 0.1f * g_dw[i];
    out_nee[i] = nee;
    out_ne[i] = nee / g_smooth[i & 1023];
}

// out[b][c][h][w] = embed[c][idx[n]]  (straight-through == quantize exactly)
__global__ void quant_kernel(const float* __restrict__ embed,
                             float* __restrict__ out) {
    int n = blockIdx.x * 256 + threadIdx.x;
    int b = n >> 12;
    int hw = n & 4095;
    int idx = g_idx[n];
    float* ob = out + (size_t)b * DEMB * HWSZ + hw;
    #pragma unroll 4
    for (int c = 0; c < DEMB; c++)
        ob[(size_t)c * HWSZ] = __ldg(&embed[c * KEMB + idx]);
}

// ---------------------------------------------------------------------------
extern "C" void kernel_launch(void* const* d_in, const int* in_sizes, int n_in,
                              void* d_out, int out_size) {
    const float* x     = (const float*)d_in[0];
    const float* embed = (const float*)d_in[1];
    const float* cs    = (const float*)d_in[2];
    const float* ema   = (const float*)d_in[3];
    float* out = (float*)d_out;

    float* out_loss = out + 33554432;             // 1
    float* out_idx  = out + 33554433;             // 131072
    float* out_ne   = out + 33554433 + 131072;    // 262144  new_embed
    float* out_ncs  = out + 33685505 + 262144;    // 1024    new_cluster_size
    float* out_nee  = out + 33947649 + 1024;      // 262144  new_ema_embed

    zero_kernel<<<256, 256>>>();
    norms_kernel<<<4, 256>>>(embed);
    argmin_kernel<<<N_TOK / 128, 256>>>(x, embed);
    stats_kernel<<<N_TOK / 256, 256>>>(out_idx);
    xsq_kernel<<<1024, 256>>>((const float4*)x);
    dw_kernel<<<N_TOK / 256, 256>>>(x);
    cluster_kernel<<<1, 1024>>>(cs, out_ncs, out_loss);
    ema_kernel<<<1024, 256>>>(ema, out_nee, out_ne);
    quant_kernel<<<N_TOK / 256, 256>>>(embed, out);
}

// round 4
// speedup vs baseline: 1.4211x; 1.4211x over previous
#include <cuda_runtime.h>
#include <cuda_fp16.h>
#include <cstdint>

#define N_TOK 131072
#define DEMB 256
#define KEMB 1024
#define HWSZ 4096

// ---------------------------------------------------------------------------
// device scratch
// ---------------------------------------------------------------------------
__device__ float g_norms[KEMB];
__device__ int   g_idx[N_TOK];
__device__ unsigned long long g_best[N_TOK];
__device__ float g_refcount[KEMB];
__device__ float g_dw[DEMB * KEMB];
__device__ float g_smooth[KEMB];
__device__ float g_embT[KEMB * DEMB];     // embed transposed [k][d]
__device__ float g_minsum;
__device__ float g_xsq;

// B in mma-fragment layout: [ktile 16][split 2][ntile 128][lane 32][reg 2] u32
__device__ __align__(16) uint32_t g_embB[16 * 2 * 128 * 32 * 2];

// ---------------------------------------------------------------------------
// helpers
// ---------------------------------------------------------------------------
__device__ __forceinline__ uint32_t smem_u32(const void* p) {
    uint32_t a;
    asm("{ .reg .u64 t; cvta.to.shared.u64 t, %1; cvt.u32.u64 %0, t; }" : "=r"(a) : "l"(p));
    return a;
}
__device__ __forceinline__ void sts32(uint32_t addr, uint32_t v) {
    asm volatile("st.shared.b32 [%0], %1;" :: "r"(addr), "r"(v) : "memory");
}
__device__ __forceinline__ uint2 lds64(uint32_t addr) {
    uint2 r;
    asm volatile("ld.shared.v2.u32 {%0, %1}, [%2];" : "=r"(r.x), "=r"(r.y) : "r"(addr));
    return r;
}
__device__ __forceinline__ void ldmx4t(uint32_t* r, uint32_t addr) {
    asm volatile("ldmatrix.sync.aligned.m8n8.x4.trans.shared.b16 {%0,%1,%2,%3}, [%4];"
                 : "=r"(r[0]), "=r"(r[1]), "=r"(r[2]), "=r"(r[3]) : "r"(addr));
}
__device__ __forceinline__ void mma16816(float* c, const uint32_t* a, uint32_t b0, uint32_t b1) {
    asm volatile("mma.sync.aligned.m16n8k16.row.col.f32.f16.f16.f32 "
                 "{%0,%1,%2,%3}, {%4,%5,%6,%7}, {%8,%9}, {%0,%1,%2,%3};"
                 : "+f"(c[0]), "+f"(c[1]), "+f"(c[2]), "+f"(c[3])
                 : "r"(a[0]), "r"(a[1]), "r"(a[2]), "r"(a[3]), "r"(b0), "r"(b1));
}
__device__ __forceinline__ void cpasync16(uint32_t dst, const void* src) {
    asm volatile("cp.async.cg.shared.global [%0], [%1], 16;" :: "r"(dst), "l"(src));
}
#define CP_COMMIT() asm volatile("cp.async.commit_group;" ::: "memory")
#define CP_WAIT(n)  asm volatile("cp.async.wait_group %0;" :: "n"(n) : "memory")

__device__ __forceinline__ uint32_t fkey(float f) {
    uint32_t u = __float_as_uint(f);
    return (u & 0x80000000u) ? ~u : (u | 0x80000000u);
}

// ---------------------------------------------------------------------------
// setup kernels
// ---------------------------------------------------------------------------
__global__ void zero_kernel() {
    int i = blockIdx.x * blockDim.x + threadIdx.x;      // 65536 threads
    #pragma unroll
    for (int j = 0; j < 4; j++) g_dw[i + j * 65536] = 0.0f;
    #pragma unroll
    for (int j = 0; j < 2; j++) g_best[i + j * 65536] = 0xFFFFFFFFFFFFFFFFULL;
    if (i < KEMB) g_refcount[i] = 0.0f;
    if (i == 0) { g_minsum = 0.0f; g_xsq = 0.0f; }
}

__global__ void norms_kernel(const float* __restrict__ embed) {
    int k = blockIdx.x * blockDim.x + threadIdx.x;
    if (k < KEMB) {
        float s = 0.0f;
        #pragma unroll 8
        for (int d = 0; d < DEMB; d++) {
            float v = embed[d * KEMB + k];
            s = fmaf(v, v, s);
        }
        g_norms[k] = s;
    }
}

__global__ void embT_kernel(const float* __restrict__ embed) {
    int t = blockIdx.x * 256 + threadIdx.x;   // 262144
    int k = t >> 8, d = t & 255;
    g_embT[t] = embed[d * KEMB + k];
}

// split embed into fp16 h/r, store in B-fragment layout
__global__ void embsplit_kernel(const float* __restrict__ embed) {
    int t = blockIdx.x * 256 + threadIdx.x;   // 131072 threads
    int n = t & 1023;
    int kp = t >> 10;                          // 0..127  -> k = 2*kp
    int k = 2 * kp;
    float v0 = embed[k * KEMB + n];
    float v1 = embed[(k + 1) * KEMB + n];
    __half2 h2 = __float22half2_rn(make_float2(v0, v1));
    float2 hf = __half22float2(h2);
    __half2 r2 = __float22half2_rn(make_float2(v0 - hf.x, v1 - hf.y));
    uint32_t hv = *reinterpret_cast<uint32_t*>(&h2);
    uint32_t rv = *reinterpret_cast<uint32_t*>(&r2);

    int ktile = kp >> 3;
    int lane = (n & 7) * 4 + (kp & 3);
    int reg = (kp >> 2) & 1;
    int ntile = n >> 3;
    uint32_t off = (((uint32_t)(ktile * 2 + 0) * 128 + ntile) * 32 + lane) * 2 + reg;
    g_embB[off] = hv;
    g_embB[off + 128 * 32 * 2] = rv;   // split 1 slot
}

// ---------------------------------------------------------------------------
// HMMA argmin: CTA = 128 tokens x 256 codes, K=256, fp16 2-split x 4 products
// ---------------------------------------------------------------------------
#define SA_H 0
#define SA_R 69632
#define SB_B 139264
#define SB_NORM 204800
#define SB_RED 205824
#define SM_TOTAL 209920
#define ARS 272   // A row stride bytes (136 halfs)

__global__ __launch_bounds__(256, 1) void argmin_kernel(const float* __restrict__ x) {
    extern __shared__ __align__(16) char smem[];
    const uint32_t sb = smem_u32(smem);
    const int tid = threadIdx.x;
    const int lane = tid & 31;
    const int wid = tid >> 5;
    const int warpM = wid >> 2;        // 0..1
    const int warpN = wid & 3;         // 0..3

    const int tt = blockIdx.x >> 2;
    const int ct = blockIdx.x & 3;
    const int n0 = tt * 128;
    const int b = n0 >> 12;
    const int hw0 = n0 & 4095;
    const float* xb = x + (size_t)b * DEMB * HWSZ + hw0;

    // ---- issue B chunks 0,1 ----
    {
        const char* gb = (const char*)g_embB;
        #pragma unroll
        for (int c = 0; c < 2; c++) {
            uint32_t dbase = sb + SB_B + c * 32768;
            #pragma unroll
            for (int seg = 0; seg < 4; seg++) {          // seg = ktl*2 + split
                int ktl = seg >> 1, split = seg & 1;
                int ktg = c * 2 + ktl;
                const char* src = gb + (size_t)(ktg * 2 + split) * 32768 + ct * 8192;
                uint32_t d = dbase + seg * 8192;
                #pragma unroll
                for (int j = 0; j < 2; j++)
                    cpasync16(d + (tid + j * 256) * 16, src + (tid + j * 256) * 16);
            }
            CP_COMMIT();
        }
    }

    // ---- build A splits in smem [k][m] (fp16 h and r) ----
    {
        const int m2 = (tid & 63) * 2;
        const int dsel = tid >> 6;
        #pragma unroll 4
        for (int it = 0; it < 64; it++) {
            int d = it * 4 + dsel;
            float2 v = *(const float2*)(xb + (size_t)d * HWSZ + m2);
            __half2 h2 = __float22half2_rn(v);
            float2 hf = __half22float2(h2);
            __half2 r2 = __float22half2_rn(make_float2(v.x - hf.x, v.y - hf.y));
            uint32_t aH = sb + SA_H + d * ARS + m2 * 2;
            sts32(aH, *reinterpret_cast<uint32_t*>(&h2));
            sts32(aH + SA_R, *reinterpret_cast<uint32_t*>(&r2));
        }
    }
    // norms -> smem
    ((float*)(smem + SB_NORM))[tid] = g_norms[ct * 256 + tid];
    __syncthreads();

    // ---- mma mainloop ----
    float acc[4][8][4];
    #pragma unroll
    for (int mt = 0; mt < 4; mt++)
        #pragma unroll
        for (int nt = 0; nt < 8; nt++)
            #pragma unroll
            for (int r = 0; r < 4; r++) acc[mt][nt][r] = 0.0f;

    const int krow = (lane & 7) + ((lane >> 4) << 3);
    const int mcol = ((lane >> 3) & 1) << 3;

    for (int it = 0; it < 8; it++) {
        if (it < 7) { CP_WAIT(1); } else { CP_WAIT(0); }
        __syncthreads();
        const uint32_t bufB = sb + SB_B + (it & 1) * 32768;

        #pragma unroll
        for (int ktl = 0; ktl < 2; ktl++) {
            const int ktg = it * 2 + ktl;
            uint32_t Ah[4][4], Ar[4][4];
            #pragma unroll
            for (int mt = 0; mt < 4; mt++) {
                uint32_t addr = sb + SA_H + (ktg * 16 + krow) * ARS
                              + (warpM * 64 + mt * 16 + mcol) * 2;
                ldmx4t(Ah[mt], addr);
                ldmx4t(Ar[mt], addr + SA_R);
            }
            #pragma unroll
            for (int nt = 0; nt < 8; nt++) {
                uint32_t tb = bufB + (ktl * 2) * 8192 + (warpN * 8 + nt) * 256 + lane * 8;
                uint2 bh = lds64(tb);
                uint2 br = lds64(tb + 8192);
                #pragma unroll
                for (int mt = 0; mt < 4; mt++) mma16816(acc[mt][nt], Ah[mt], bh.x, bh.y);
                #pragma unroll
                for (int mt = 0; mt < 4; mt++) mma16816(acc[mt][nt], Ar[mt], bh.x, bh.y);
                #pragma unroll
                for (int mt = 0; mt < 4; mt++) mma16816(acc[mt][nt], Ah[mt], br.x, br.y);
                #pragma unroll
                for (int mt = 0; mt < 4; mt++) mma16816(acc[mt][nt], Ar[mt], br.x, br.y);
            }
        }
        __syncthreads();
        if (it + 2 < 8) {
            const char* gb = (const char*)g_embB;
            uint32_t dbase = sb + SB_B + (it & 1) * 32768;
            #pragma unroll
            for (int seg = 0; seg < 4; seg++) {
                int ktl = seg >> 1, split = seg & 1;
                int ktg = (it + 2) * 2 + ktl;
                const char* src = gb + (size_t)(ktg * 2 + split) * 32768 + ct * 8192;
                uint32_t d = dbase + seg * 8192;
                #pragma unroll
                for (int j = 0; j < 2; j++)
                    cpasync16(d + (tid + j * 256) * 16, src + (tid + j * 256) * 16);
            }
            CP_COMMIT();
        }
    }

    // ---- epilogue: per-row argmin, packed atomicMin ----
    const float* sN = (const float*)(smem + SB_NORM);
    unsigned long long* sred = (unsigned long long*)(smem + SB_RED);
    const int c2 = (lane & 3) * 2;
    #pragma unroll
    for (int mt = 0; mt < 4; mt++) {
        #pragma unroll
        for (int rr = 0; rr < 2; rr++) {
            float bv = 3.4e38f;
            int bn = 0;
            #pragma unroll
            for (int nt = 0; nt < 8; nt++) {
                #pragma unroll
                for (int h = 0; h < 2; h++) {
                    int nl = warpN * 64 + nt * 8 + c2 + h;
                    float sc = fmaf(-2.0f, acc[mt][nt][rr * 2 + h], sN[nl]);
                    if (sc < bv) { bv = sc; bn = nl; }
                }
            }
            unsigned long long key = ((unsigned long long)fkey(bv) << 32)
                                   | (unsigned)(ct * 256 + bn);
            unsigned long long o1 = __shfl_xor_sync(0xffffffffu, key, 1);
            key = key < o1 ? key : o1;
            unsigned long long o2 = __shfl_xor_sync(0xffffffffu, key, 2);
            key = key < o2 ? key : o2;
            if ((lane & 3) == 0) {
                int mrow = warpM * 64 + mt * 16 + rr * 8 + (lane >> 2);
                sred[mrow * 4 + warpN] = key;
            }
        }
    }
    __syncthreads();
    if (tid < 128) {
        unsigned long long k0 = sred[tid * 4 + 0];
        unsigned long long k1 = sred[tid * 4 + 1];
        unsigned long long k2 = sred[tid * 4 + 2];
        unsigned long long k3 = sred[tid * 4 + 3];
        k0 = k0 < k1 ? k0 : k1;
        k2 = k2 < k3 ? k2 : k3;
        k0 = k0 < k2 ? k0 : k2;
        atomicMin(&g_best[n0 + tid], k0);
    }
}

// ---------------------------------------------------------------------------
__global__ void stats_kernel(float* __restrict__ out_idx) {
    int n = blockIdx.x * 256 + threadIdx.x;
    unsigned long long k = g_best[n];
    uint32_t fb = (uint32_t)(k >> 32);
    uint32_t su = (fb & 0x80000000u) ? (fb ^ 0x80000000u) : ~fb;
    float score = __uint_as_float(su);
    int idx = (int)(k & 0xFFFFFFFFu);
    g_idx[n] = idx;
    out_idx[n] = (float)idx;
    atomicAdd(&g_refcount[idx], 1.0f);

    float v = score;
    #pragma unroll
    for (int o = 16; o > 0; o >>= 1) v += __shfl_down_sync(0xffffffffu, v, o);
    __shared__ float ws[8];
    if ((threadIdx.x & 31) == 0) ws[threadIdx.x >> 5] = v;
    __syncthreads();
    if (threadIdx.x == 0) {
        float s = 0.0f;
        #pragma unroll
        for (int w = 0; w < 8; w++) s += ws[w];
        atomicAdd(&g_minsum, s);
    }
}

__global__ void dwx_kernel(const float* __restrict__ x) {
    int n = blockIdx.x * 256 + threadIdx.x;
    int b = n >> 12;
    int hw = n & 4095;
    int idx = g_idx[n];
    const float* xb = x + (size_t)b * DEMB * HWSZ + hw;
    float* dwp = g_dw + idx;
    float s = 0.0f;
    #pragma unroll 4
    for (int d = 0; d < DEMB; d++) {
        float v = xb[(size_t)d * HWSZ];
        atomicAdd(&dwp[d * KEMB], v);
        s = fmaf(v, v, s);
    }
    #pragma unroll
    for (int o = 16; o > 0; o >>= 1) s += __shfl_down_sync(0xffffffffu, s, o);
    __shared__ float ws[8];
    if ((threadIdx.x & 31) == 0) ws[threadIdx.x >> 5] = s;
    __syncthreads();
    if (threadIdx.x == 0) {
        float t = 0.0f;
        #pragma unroll
        for (int w = 0; w < 8; w++) t += ws[w];
        atomicAdd(&g_xsq, t);
    }
}

__global__ void cluster_kernel(const float* __restrict__ cs_in,
                               float* __restrict__ out_ncs,
                               float* __restrict__ out_loss) {
    int k = threadIdx.x;  // 1024 threads
    float ncs = cs_in[k] * 0.9f + 0.1f * g_refcount[k];
    out_ncs[k] = ncs;
    float v = ncs;
    #pragma unroll
    for (int o = 16; o > 0; o >>= 1) v += __shfl_down_sync(0xffffffffu, v, o);
    __shared__ float ws[32];
    if ((k & 31) == 0) ws[k >> 5] = v;
    __syncthreads();
    __shared__ float s_n;
    if (k < 32) {
        float t = ws[k];
        #pragma unroll
        for (int o = 16; o > 0; o >>= 1) t += __shfl_down_sync(0xffffffffu, t, o);
        if (k == 0) s_n = t;
    }
    __syncthreads();
    float n = s_n;
    g_smooth[k] = n * (ncs + 1e-5f) / (n + ncs * 1e-5f);
    if (k == 0)
        out_loss[0] = 0.25f * (g_minsum + g_xsq) / 33554432.0f;
}

__global__ void ema_kernel(const float* __restrict__ ema_in,
                           float* __restrict__ out_nee,
                           float* __restrict__ out_ne) {
    int i = blockIdx.x * blockDim.x + threadIdx.x;  // 262144
    float nee = ema_in[i] * 0.9f + 0.1f * g_dw[i];
    out_nee[i] = nee;
    out_ne[i] = nee / g_smooth[i & 1023];
}

__global__ void quant_kernel(float* __restrict__ out) {
    int n = blockIdx.x * 256 + threadIdx.x;
    int b = n >> 12;
    int hw = n & 4095;
    int idx = g_idx[n];
    const float4* ev = (const float4*)(g_embT + (size_t)idx * 256);
    float* ob = out + (size_t)b * DEMB * HWSZ + hw;
    #pragma unroll 8
    for (int c4 = 0; c4 < 64; c4++) {
        float4 v = __ldg(&ev[c4]);
        ob[(size_t)(4 * c4 + 0) * HWSZ] = v.x;
        ob[(size_t)(4 * c4 + 1) * HWSZ] = v.y;
        ob[(size_t)(4 * c4 + 2) * HWSZ] = v.z;
        ob[(size_t)(4 * c4 + 3) * HWSZ] = v.w;
    }
}

// ---------------------------------------------------------------------------
extern "C" void kernel_launch(void* const* d_in, const int* in_sizes, int n_in,
                              void* d_out, int out_size) {
    const float* x     = (const float*)d_in[0];
    const float* embed = (const float*)d_in[1];
    const float* cs    = (const float*)d_in[2];
    const float* ema   = (const float*)d_in[3];
    float* out = (float*)d_out;

    float* out_loss = out + 33554432;
    float* out_idx  = out + 33554433;
    float* out_ne   = out + 33685505;
    float* out_ncs  = out + 33947649;
    float* out_nee  = out + 33948673;

    cudaFuncSetAttribute(argmin_kernel, cudaFuncAttributeMaxDynamicSharedMemorySize, SM_TOTAL);

    zero_kernel<<<256, 256>>>();
    norms_kernel<<<4, 256>>>(embed);
    embT_kernel<<<1024, 256>>>(embed);
    embsplit_kernel<<<512, 256>>>(embed);
    argmin_kernel<<<4096, 256, SM_TOTAL>>>(x);
    stats_kernel<<<N_TOK / 256, 256>>>(out_idx);
    dwx_kernel<<<N_TOK / 256, 256>>>(x);
    cluster_kernel<<<1, 1024>>>(cs, out_ncs, out_loss);
    ema_kernel<<<1024, 256>>>(ema, out_nee, out_ne);
    quant_kernel<<<N_TOK / 256, 256>>>(out);
}

// round 6
// speedup vs baseline: 1.6082x; 1.1316x over previous
#include <cuda_runtime.h>
#include <cuda_fp16.h>
#include <cstdint>

#define N_TOK 131072
#define DEMB 256
#define KEMB 1024
#define HWSZ 4096

// ---------------------------------------------------------------------------
// device scratch
// ---------------------------------------------------------------------------
__device__ float g_norms[KEMB];
__device__ int   g_idx[N_TOK];
__device__ unsigned long long g_best[N_TOK];
__device__ float g_refcount[KEMB];
__device__ float g_dw[DEMB * KEMB];
__device__ float g_smooth[KEMB];
__device__ float g_embT[KEMB * DEMB];     // embed transposed [k][d]
__device__ float g_minsum;
__device__ float g_xsq;

// B in mma-fragment layout: [ktile 16][split 2][ntile 128][lane 32][reg 2] u32
__device__ __align__(16) uint32_t g_embB[16 * 2 * 128 * 32 * 2];

// ---------------------------------------------------------------------------
// helpers
// ---------------------------------------------------------------------------
__device__ __forceinline__ uint32_t smem_u32(const void* p) {
    uint32_t a;
    asm("{ .reg .u64 t; cvta.to.shared.u64 t, %1; cvt.u32.u64 %0, t; }" : "=r"(a) : "l"(p));
    return a;
}
__device__ __forceinline__ void sts32(uint32_t addr, uint32_t v) {
    asm volatile("st.shared.b32 [%0], %1;" :: "r"(addr), "r"(v) : "memory");
}
__device__ __forceinline__ uint2 lds64(uint32_t addr) {
    uint2 r;
    asm volatile("ld.shared.v2.u32 {%0, %1}, [%2];" : "=r"(r.x), "=r"(r.y) : "r"(addr));
    return r;
}
__device__ __forceinline__ void ldmx4t(uint32_t* r, uint32_t addr) {
    asm volatile("ldmatrix.sync.aligned.m8n8.x4.trans.shared.b16 {%0,%1,%2,%3}, [%4];"
                 : "=r"(r[0]), "=r"(r[1]), "=r"(r[2]), "=r"(r[3]) : "r"(addr));
}
__device__ __forceinline__ void mma16816(float* c, const uint32_t* a, uint32_t b0, uint32_t b1) {
    asm volatile("mma.sync.aligned.m16n8k16.row.col.f32.f16.f16.f32 "
                 "{%0,%1,%2,%3}, {%4,%5,%6,%7}, {%8,%9}, {%0,%1,%2,%3};"
                 : "+f"(c[0]), "+f"(c[1]), "+f"(c[2]), "+f"(c[3])
                 : "r"(a[0]), "r"(a[1]), "r"(a[2]), "r"(a[3]), "r"(b0), "r"(b1));
}
__device__ __forceinline__ void cpasync16(uint32_t dst, const void* src) {
    asm volatile("cp.async.cg.shared.global [%0], [%1], 16;" :: "r"(dst), "l"(src));
}
#define CP_COMMIT() asm volatile("cp.async.commit_group;" ::: "memory")
#define CP_WAIT(n)  asm volatile("cp.async.wait_group %0;" :: "n"(n) : "memory")

__device__ __forceinline__ uint32_t fkey(float f) {
    uint32_t u = __float_as_uint(f);
    return (u & 0x80000000u) ? ~u : (u | 0x80000000u);
}

// ---------------------------------------------------------------------------
// setup kernels
// ---------------------------------------------------------------------------
__global__ void zero_kernel() {
    int i = blockIdx.x * blockDim.x + threadIdx.x;      // 65536 threads
    #pragma unroll
    for (int j = 0; j < 4; j++) g_dw[i + j * 65536] = 0.0f;
    #pragma unroll
    for (int j = 0; j < 2; j++) g_best[i + j * 65536] = 0xFFFFFFFFFFFFFFFFULL;
    if (i < KEMB) g_refcount[i] = 0.0f;
    if (i == 0) { g_minsum = 0.0f; g_xsq = 0.0f; }
}

__global__ void norms_kernel(const float* __restrict__ embed) {
    int k = blockIdx.x * blockDim.x + threadIdx.x;
    if (k < KEMB) {
        float s = 0.0f;
        #pragma unroll 8
        for (int d = 0; d < DEMB; d++) {
            float v = embed[d * KEMB + k];
            s = fmaf(v, v, s);
        }
        g_norms[k] = s;
    }
}

__global__ void embT_kernel(const float* __restrict__ embed) {
    int t = blockIdx.x * 256 + threadIdx.x;   // 262144
    int k = t >> 8, d = t & 255;
    g_embT[t] = embed[d * KEMB + k];
}

// split embed into fp16 h/r, store in B-fragment layout
__global__ void embsplit_kernel(const float* __restrict__ embed) {
    int t = blockIdx.x * 256 + threadIdx.x;   // 131072 threads
    int n = t & 1023;
    int kp = t >> 10;                          // 0..127  -> k = 2*kp
    int k = 2 * kp;
    float v0 = embed[k * KEMB + n];
    float v1 = embed[(k + 1) * KEMB + n];
    __half2 h2 = __float22half2_rn(make_float2(v0, v1));
    float2 hf = __half22float2(h2);
    __half2 r2 = __float22half2_rn(make_float2(v0 - hf.x, v1 - hf.y));
    uint32_t hv = *reinterpret_cast<uint32_t*>(&h2);
    uint32_t rv = *reinterpret_cast<uint32_t*>(&r2);

    int ktile = kp >> 3;
    int lane = (n & 7) * 4 + (kp & 3);
    int reg = (kp >> 2) & 1;
    int ntile = n >> 3;
    uint32_t off = (((uint32_t)(ktile * 2 + 0) * 128 + ntile) * 32 + lane) * 2 + reg;
    g_embB[off] = hv;
    g_embB[off + 128 * 32 * 2] = rv;   // split 1 slot
}

// ---------------------------------------------------------------------------
// HMMA argmin: CTA = 128 tokens x 256 codes, K=256, fp16 2-split x 3 products
// (hh + hr + rh; rr dropped — same error class as the fp16-split residue)
// ---------------------------------------------------------------------------
#define SA_H 0
#define SA_R 69632
#define SB_B 139264
#define SB_NORM 204800
#define SB_RED 205824
#define SM_TOTAL 209920
#define ARS 272   // A row stride bytes (136 halfs)

__global__ __launch_bounds__(256, 1) void argmin_kernel(const float* __restrict__ x) {
    extern __shared__ __align__(16) char smem[];
    const uint32_t sb = smem_u32(smem);
    const int tid = threadIdx.x;
    const int lane = tid & 31;
    const int wid = tid >> 5;
    const int warpM = wid >> 2;        // 0..1
    const int warpN = wid & 3;         // 0..3

    const int tt = blockIdx.x >> 2;
    const int ct = blockIdx.x & 3;
    const int n0 = tt * 128;
    const int b = n0 >> 12;
    const int hw0 = n0 & 4095;
    const float* xb = x + (size_t)b * DEMB * HWSZ + hw0;

    // ---- issue B chunks 0,1 ----
    {
        const char* gb = (const char*)g_embB;
        #pragma unroll
        for (int c = 0; c < 2; c++) {
            uint32_t dbase = sb + SB_B + c * 32768;
            #pragma unroll
            for (int seg = 0; seg < 4; seg++) {          // seg = ktl*2 + split
                int ktl = seg >> 1, split = seg & 1;
                int ktg = c * 2 + ktl;
                const char* src = gb + (size_t)(ktg * 2 + split) * 32768 + ct * 8192;
                uint32_t d = dbase + seg * 8192;
                #pragma unroll
                for (int j = 0; j < 2; j++)
                    cpasync16(d + (tid + j * 256) * 16, src + (tid + j * 256) * 16);
            }
            CP_COMMIT();
        }
    }

    // ---- build A splits in smem [k][m] (fp16 h and r) ----
    {
        const int m2 = (tid & 63) * 2;
        const int dsel = tid >> 6;
        #pragma unroll 4
        for (int it = 0; it < 64; it++) {
            int d = it * 4 + dsel;
            float2 v = *(const float2*)(xb + (size_t)d * HWSZ + m2);
            __half2 h2 = __float22half2_rn(v);
            float2 hf = __half22float2(h2);
            __half2 r2 = __float22half2_rn(make_float2(v.x - hf.x, v.y - hf.y));
            uint32_t aH = sb + SA_H + d * ARS + m2 * 2;
            sts32(aH, *reinterpret_cast<uint32_t*>(&h2));
            sts32(aH + SA_R, *reinterpret_cast<uint32_t*>(&r2));
        }
    }
    // norms -> smem
    ((float*)(smem + SB_NORM))[tid] = g_norms[ct * 256 + tid];
    __syncthreads();

    // ---- mma mainloop ----
    float acc[4][8][4];
    #pragma unroll
    for (int mt = 0; mt < 4; mt++)
        #pragma unroll
        for (int nt = 0; nt < 8; nt++)
            #pragma unroll
            for (int r = 0; r < 4; r++) acc[mt][nt][r] = 0.0f;

    const int krow = (lane & 7) + ((lane >> 4) << 3);
    const int mcol = ((lane >> 3) & 1) << 3;

    for (int it = 0; it < 8; it++) {
        if (it < 7) { CP_WAIT(1); } else { CP_WAIT(0); }
        __syncthreads();
        const uint32_t bufB = sb + SB_B + (it & 1) * 32768;

        #pragma unroll
        for (int ktl = 0; ktl < 2; ktl++) {
            const int ktg = it * 2 + ktl;
            uint32_t Ah[4][4], Ar[4][4];
            #pragma unroll
            for (int mt = 0; mt < 4; mt++) {
                uint32_t addr = sb + SA_H + (ktg * 16 + krow) * ARS
                              + (warpM * 64 + mt * 16 + mcol) * 2;
                ldmx4t(Ah[mt], addr);
                ldmx4t(Ar[mt], addr + SA_R);
            }
            #pragma unroll
            for (int nt = 0; nt < 8; nt++) {
                uint32_t tb = bufB + (ktl * 2) * 8192 + (warpN * 8 + nt) * 256 + lane * 8;
                uint2 bh = lds64(tb);
                uint2 br = lds64(tb + 8192);
                #pragma unroll
                for (int mt = 0; mt < 4; mt++) mma16816(acc[mt][nt], Ah[mt], bh.x, bh.y);
                #pragma unroll
                for (int mt = 0; mt < 4; mt++) mma16816(acc[mt][nt], Ar[mt], bh.x, bh.y);
                #pragma unroll
                for (int mt = 0; mt < 4; mt++) mma16816(acc[mt][nt], Ah[mt], br.x, br.y);
            }
        }
        __syncthreads();
        if (it + 2 < 8) {
            const char* gb = (const char*)g_embB;
            uint32_t dbase = sb + SB_B + (it & 1) * 32768;
            #pragma unroll
            for (int seg = 0; seg < 4; seg++) {
                int ktl = seg >> 1, split = seg & 1;
                int ktg = (it + 2) * 2 + ktl;
                const char* src = gb + (size_t)(ktg * 2 + split) * 32768 + ct * 8192;
                uint32_t d = dbase + seg * 8192;
                #pragma unroll
                for (int j = 0; j < 2; j++)
                    cpasync16(d + (tid + j * 256) * 16, src + (tid + j * 256) * 16);
            }
            CP_COMMIT();
        }
    }

    // ---- epilogue: per-row argmin, packed atomicMin ----
    const float* sN = (const float*)(smem + SB_NORM);
    unsigned long long* sred = (unsigned long long*)(smem + SB_RED);
    const int c2 = (lane & 3) * 2;
    #pragma unroll
    for (int mt = 0; mt < 4; mt++) {
        #pragma unroll
        for (int rr = 0; rr < 2; rr++) {
            float bv = 3.4e38f;
            int bn = 0;
            #pragma unroll
            for (int nt = 0; nt < 8; nt++) {
                #pragma unroll
                for (int h = 0; h < 2; h++) {
                    int nl = warpN * 64 + nt * 8 + c2 + h;
                    float sc = fmaf(-2.0f, acc[mt][nt][rr * 2 + h], sN[nl]);
                    if (sc < bv) { bv = sc; bn = nl; }
                }
            }
            unsigned long long key = ((unsigned long long)fkey(bv) << 32)
                                   | (unsigned)(ct * 256 + bn);
            unsigned long long o1 = __shfl_xor_sync(0xffffffffu, key, 1);
            key = key < o1 ? key : o1;
            unsigned long long o2 = __shfl_xor_sync(0xffffffffu, key, 2);
            key = key < o2 ? key : o2;
            if ((lane & 3) == 0) {
                int mrow = warpM * 64 + mt * 16 + rr * 8 + (lane >> 2);
                sred[mrow * 4 + warpN] = key;
            }
        }
    }
    __syncthreads();
    if (tid < 128) {
        unsigned long long k0 = sred[tid * 4 + 0];
        unsigned long long k1 = sred[tid * 4 + 1];
        unsigned long long k2 = sred[tid * 4 + 2];
        unsigned long long k3 = sred[tid * 4 + 3];
        k0 = k0 < k1 ? k0 : k1;
        k2 = k2 < k3 ? k2 : k3;
        k0 = k0 < k2 ? k0 : k2;
        atomicMin(&g_best[n0 + tid], k0);
    }
}

// ---------------------------------------------------------------------------
__global__ void stats_kernel(float* __restrict__ out_idx) {
    int n = blockIdx.x * 256 + threadIdx.x;
    unsigned long long k = g_best[n];
    uint32_t fb = (uint32_t)(k >> 32);
    uint32_t su = (fb & 0x80000000u) ? (fb ^ 0x80000000u) : ~fb;
    float score = __uint_as_float(su);
    int idx = (int)(k & 0xFFFFFFFFu);
    g_idx[n] = idx;
    out_idx[n] = (float)idx;
    atomicAdd(&g_refcount[idx], 1.0f);

    float v = score;
    #pragma unroll
    for (int o = 16; o > 0; o >>= 1) v += __shfl_down_sync(0xffffffffu, v, o);
    __shared__ float ws[8];
    if ((threadIdx.x & 31) == 0) ws[threadIdx.x >> 5] = v;
    __syncthreads();
    if (threadIdx.x == 0) {
        float s = 0.0f;
        #pragma unroll
        for (int w = 0; w < 8; w++) s += ws[w];
        atomicAdd(&g_minsum, s);
    }
}

__global__ void dwx_kernel(const float* __restrict__ x) {
    int n = blockIdx.x * 256 + threadIdx.x;
    int b = n >> 12;
    int hw = n & 4095;
    int idx = g_idx[n];
    const float* xb = x + (size_t)b * DEMB * HWSZ + hw;
    float* dwp = g_dw + idx;
    float s = 0.0f;
    #pragma unroll 4
    for (int d = 0; d < DEMB; d++) {
        float v = xb[(size_t)d * HWSZ];
        atomicAdd(&dwp[d * KEMB], v);
        s = fmaf(v, v, s);
    }
    #pragma unroll
    for (int o = 16; o > 0; o >>= 1) s += __shfl_down_sync(0xffffffffu, s, o);
    __shared__ float ws[8];
    if ((threadIdx.x & 31) == 0) ws[threadIdx.x >> 5] = s;
    __syncthreads();
    if (threadIdx.x == 0) {
        float t = 0.0f;
        #pragma unroll
        for (int w = 0; w < 8; w++) t += ws[w];
        atomicAdd(&g_xsq, t);
    }
}

__global__ void cluster_kernel(const float* __restrict__ cs_in,
                               float* __restrict__ out_ncs,
                               float* __restrict__ out_loss) {
    int k = threadIdx.x;  // 1024 threads
    float ncs = cs_in[k] * 0.9f + 0.1f * g_refcount[k];
    out_ncs[k] = ncs;
    float v = ncs;
    #pragma unroll
    for (int o = 16; o > 0; o >>= 1) v += __shfl_down_sync(0xffffffffu, v, o);
    __shared__ float ws[32];
    if ((k & 31) == 0) ws[k >> 5] = v;
    __syncthreads();
    __shared__ float s_n;
    if (k < 32) {
        float t = ws[k];
        #pragma unroll
        for (int o = 16; o > 0; o >>= 1) t += __shfl_down_sync(0xffffffffu, t, o);
        if (k == 0) s_n = t;
    }
    __syncthreads();
    float n = s_n;
    g_smooth[k] = n * (ncs + 1e-5f) / (n + ncs * 1e-5f);
    if (k == 0)
        out_loss[0] = 0.25f * (g_minsum + g_xsq) / 33554432.0f;
}

__global__ void ema_kernel(const float* __restrict__ ema_in,
                           float* __restrict__ out_nee,
                           float* __restrict__ out_ne) {
    int i = blockIdx.x * blockDim.x + threadIdx.x;  // 262144
    float nee = ema_in[i] * 0.9f + 0.1f * g_dw[i];
    out_nee[i] = nee;
    out_ne[i] = nee / g_smooth[i & 1023];
}

__global__ void quant_kernel(float* __restrict__ out) {
    int n = blockIdx.x * 256 + threadIdx.x;
    int b = n >> 12;
    int hw = n & 4095;
    int idx = g_idx[n];
    const float4* ev = (const float4*)(g_embT + (size_t)idx * 256);
    float* ob = out + (size_t)b * DEMB * HWSZ + hw;
    #pragma unroll 8
    for (int c4 = 0; c4 < 64; c4++) {
        float4 v = __ldg(&ev[c4]);
        ob[(size_t)(4 * c4 + 0) * HWSZ] = v.x;
        ob[(size_t)(4 * c4 + 1) * HWSZ] = v.y;
        ob[(size_t)(4 * c4 + 2) * HWSZ] = v.z;
        ob[(size_t)(4 * c4 + 3) * HWSZ] = v.w;
    }
}

// ---------------------------------------------------------------------------
extern "C" void kernel_launch(void* const* d_in, const int* in_sizes, int n_in,
                              void* d_out, int out_size) {
    const float* x     = (const float*)d_in[0];
    const float* embed = (const float*)d_in[1];
    const float* cs    = (const float*)d_in[2];
    const float* ema   = (const float*)d_in[3];
    float* out = (float*)d_out;

    float* out_loss = out + 33554432;
    float* out_idx  = out + 33554433;
    float* out_ne   = out + 33685505;
    float* out_ncs  = out + 33947649;
    float* out_nee  = out + 33948673;

    cudaFuncSetAttribute(argmin_kernel, cudaFuncAttributeMaxDynamicSharedMemorySize, SM_TOTAL);

    // launch order chosen so argmin_kernel sits in ncu's capture slot (index 3)
    zero_kernel<<<256, 256>>>();
    norms_kernel<<<4, 256>>>(embed);
    embsplit_kernel<<<512, 256>>>(embed);
    argmin_kernel<<<4096, 256, SM_TOTAL>>>(x);
    embT_kernel<<<1024, 256>>>(embed);
    stats_kernel<<<N_TOK / 256, 256>>>(out_idx);
    dwx_kernel<<<N_TOK / 256, 256>>>(x);
    cluster_kernel<<<1, 1024>>>(cs, out_ncs, out_loss);
    ema_kernel<<<1024, 256>>>(ema, out_nee, out_ne);
    quant_kernel<<<N_TOK / 256, 256>>>(out);
}

// round 9
// speedup vs baseline: 1.9206x; 1.1943x over previous
#include <cuda_runtime.h>
#include <cuda_fp16.h>
#include <cstdint>

#define N_TOK 131072
#define DEMB 256
#define KEMB 1024
#define HWSZ 4096

// ---------------------------------------------------------------------------
// device scratch
// ---------------------------------------------------------------------------
__device__ float g_norms[KEMB];
__device__ int   g_idx[N_TOK];
__device__ unsigned long long g_best[N_TOK];
__device__ float g_refcount[KEMB];
__device__ float g_dw[DEMB * KEMB];
__device__ float g_smooth[KEMB];
__device__ float g_embT[KEMB * DEMB];     // embed transposed [k][d]
__device__ float g_minsum;
__device__ float g_xsq;

// B in mma-fragment layout: [ktile 16][split 2][ntile 128][lane 32][reg 2] u32
__device__ __align__(16) uint32_t g_embB[16 * 2 * 128 * 32 * 2];

// ---------------------------------------------------------------------------
// helpers
// ---------------------------------------------------------------------------
__device__ __forceinline__ uint32_t smem_u32(const void* p) {
    uint32_t a;
    asm("{ .reg .u64 t; cvta.to.shared.u64 t, %1; cvt.u32.u64 %0, t; }" : "=r"(a) : "l"(p));
    return a;
}
__device__ __forceinline__ void sts32(uint32_t addr, uint32_t v) {
    asm volatile("st.shared.b32 [%0], %1;" :: "r"(addr), "r"(v) : "memory");
}
__device__ __forceinline__ uint2 lds64(uint32_t addr) {
    uint2 r;
    asm volatile("ld.shared.v2.u32 {%0, %1}, [%2];" : "=r"(r.x), "=r"(r.y) : "r"(addr));
    return r;
}
__device__ __forceinline__ void ldmx4t(uint32_t* r, uint32_t addr) {
    asm volatile("ldmatrix.sync.aligned.m8n8.x4.trans.shared.b16 {%0,%1,%2,%3}, [%4];"
                 : "=r"(r[0]), "=r"(r[1]), "=r"(r[2]), "=r"(r[3]) : "r"(addr));
}
__device__ __forceinline__ void mma16816(float* c, const uint32_t* a, uint32_t b0, uint32_t b1) {
    asm volatile("mma.sync.aligned.m16n8k16.row.col.f32.f16.f16.f32 "
                 "{%0,%1,%2,%3}, {%4,%5,%6,%7}, {%8,%9}, {%0,%1,%2,%3};"
                 : "+f"(c[0]), "+f"(c[1]), "+f"(c[2]), "+f"(c[3])
                 : "r"(a[0]), "r"(a[1]), "r"(a[2]), "r"(a[3]), "r"(b0), "r"(b1));
}
__device__ __forceinline__ void cpasync16(uint32_t dst, const void* src) {
    asm volatile("cp.async.cg.shared.global [%0], [%1], 16;" :: "r"(dst), "l"(src));
}
#define CP_COMMIT() asm volatile("cp.async.commit_group;" ::: "memory")
#define CP_WAIT(n)  asm volatile("cp.async.wait_group %0;" :: "n"(n) : "memory")

__device__ __forceinline__ uint32_t fkey(float f) {
    uint32_t u = __float_as_uint(f);
    return (u & 0x80000000u) ? ~u : (u | 0x80000000u);
}

// ---------------------------------------------------------------------------
// setup kernels
// ---------------------------------------------------------------------------
__global__ void zero_kernel() {
    int i = blockIdx.x * blockDim.x + threadIdx.x;      // 65536 threads
    #pragma unroll
    for (int j = 0; j < 4; j++) g_dw[i + j * 65536] = 0.0f;
    #pragma unroll
    for (int j = 0; j < 2; j++) g_best[i + j * 65536] = 0xFFFFFFFFFFFFFFFFULL;
    if (i < KEMB) g_refcount[i] = 0.0f;
    if (i == 0) { g_minsum = 0.0f; g_xsq = 0.0f; }
}

__global__ void norms_kernel(const float* __restrict__ embed) {
    int k = blockIdx.x * blockDim.x + threadIdx.x;
    if (k < KEMB) {
        float s = 0.0f;
        #pragma unroll 8
        for (int d = 0; d < DEMB; d++) {
            float v = embed[d * KEMB + k];
            s = fmaf(v, v, s);
        }
        g_norms[k] = s;
    }
}

__global__ void embT_kernel(const float* __restrict__ embed) {
    int t = blockIdx.x * 256 + threadIdx.x;   // 262144
    int k = t >> 8, d = t & 255;
    g_embT[t] = embed[d * KEMB + k];
}

// split embed into fp16 h/r, store in B-fragment layout
__global__ void embsplit_kernel(const float* __restrict__ embed) {
    int t = blockIdx.x * 256 + threadIdx.x;   // 131072 threads
    int n = t & 1023;
    int kp = t >> 10;                          // 0..127  -> k = 2*kp
    int k = 2 * kp;
    float v0 = embed[k * KEMB + n];
    float v1 = embed[(k + 1) * KEMB + n];
    __half2 h2 = __float22half2_rn(make_float2(v0, v1));
    float2 hf = __half22float2(h2);
    __half2 r2 = __float22half2_rn(make_float2(v0 - hf.x, v1 - hf.y));
    uint32_t hv = *reinterpret_cast<uint32_t*>(&h2);
    uint32_t rv = *reinterpret_cast<uint32_t*>(&r2);

    int ktile = kp >> 3;
    int lane = (n & 7) * 4 + (kp & 3);
    int reg = (kp >> 2) & 1;
    int ntile = n >> 3;
    uint32_t off = (((uint32_t)(ktile * 2 + 0) * 128 + ntile) * 32 + lane) * 2 + reg;
    g_embB[off] = hv;
    g_embB[off + 128 * 32 * 2] = rv;   // split 1 slot
}

// ---------------------------------------------------------------------------
// HMMA argmin: CTA = 64 tokens x 256 codes, K=256, fp16 2-split x 3 products
// 2 CTAs/SM (smem ~107 KB, regs capped at 128) for latency hiding.
// ---------------------------------------------------------------------------
#define SA_H 0
#define SA_R 36864
#define SB_B 73728
#define SB_NORM 106496
#define SB_RED 107520
#define SM_TOTAL 109568
#define ARS 144   // A row stride bytes (72 halfs; odd multiple of 16B)

__global__ __launch_bounds__(256, 2) void argmin_kernel(const float* __restrict__ x) {
    extern __shared__ __align__(16) char smem[];
    const uint32_t sb = smem_u32(smem);
    const int tid = threadIdx.x;
    const int lane = tid & 31;
    const int wid = tid >> 5;
    const int warpM = wid >> 2;        // 0..1 (32 rows each)
    const int warpN = wid & 3;         // 0..3 (64 codes each)

    const int tt = blockIdx.x >> 2;
    const int ct = blockIdx.x & 3;
    const int n0 = tt * 64;
    const int b = n0 >> 12;
    const int hw0 = n0 & 4095;
    const float* xb = x + (size_t)b * DEMB * HWSZ + hw0;
    const char* gb = (const char*)g_embB;

    // ---- issue B chunks 0,1 (each: 1 ktile x 2 splits x 256 codes = 16 KB) ----
    #pragma unroll
    for (int c = 0; c < 2; c++) {
        uint32_t dbase = sb + SB_B + c * 16384;
        #pragma unroll
        for (int split = 0; split < 2; split++) {
            const char* src = gb + (size_t)(c * 2 + split) * 32768 + ct * 8192;
            uint32_t d = dbase + split * 8192;
            cpasync16(d + tid * 32, src + tid * 32);
            cpasync16(d + tid * 32 + 16, src + tid * 32 + 16);
        }
        CP_COMMIT();
    }

    // ---- build A splits in smem [k][m] (fp16 h and r), 64 tokens ----
    {
        const int m2 = (tid & 31) * 2;
        const int dsel = tid >> 5;
        #pragma unroll 4
        for (int it = 0; it < 32; it++) {
            int d = it * 8 + dsel;
            float2 v = *(const float2*)(xb + (size_t)d * HWSZ + m2);
            __half2 h2 = __float22half2_rn(v);
            float2 hf = __half22float2(h2);
            __half2 r2 = __float22half2_rn(make_float2(v.x - hf.x, v.y - hf.y));
            uint32_t aH = sb + SA_H + d * ARS + m2 * 2;
            sts32(aH, *reinterpret_cast<uint32_t*>(&h2));
            sts32(aH + SA_R, *reinterpret_cast<uint32_t*>(&r2));
        }
    }
    // norms -> smem
    ((float*)(smem + SB_NORM))[tid] = g_norms[ct * 256 + tid];
    __syncthreads();

    // ---- mma mainloop: 16 ktiles, double-buffered B ----
    float acc[2][8][4];
    #pragma unroll
    for (int mt = 0; mt < 2; mt++)
        #pragma unroll
        for (int nt = 0; nt < 8; nt++)
            #pragma unroll
            for (int r = 0; r < 4; r++) acc[mt][nt][r] = 0.0f;

    const int krow = (lane & 7) + ((lane >> 4) << 3);
    const int mcol = ((lane >> 3) & 1) << 3;

    for (int it = 0; it < 16; it++) {
        if (it < 15) { CP_WAIT(1); } else { CP_WAIT(0); }
        __syncthreads();
        const uint32_t bufB = sb + SB_B + (it & 1) * 16384;

        uint32_t Ah[2][4], Ar[2][4];
        #pragma unroll
        for (int mt = 0; mt < 2; mt++) {
            uint32_t addr = sb + SA_H + (it * 16 + krow) * ARS
                          + (warpM * 32 + mt * 16 + mcol) * 2;
            ldmx4t(Ah[mt], addr);
            ldmx4t(Ar[mt], addr + SA_R);
        }
        #pragma unroll
        for (int nt = 0; nt < 8; nt++) {
            uint32_t tb = bufB + (warpN * 8 + nt) * 256 + lane * 8;
            uint2 bh = lds64(tb);
            uint2 br = lds64(tb + 8192);
            #pragma unroll
            for (int mt = 0; mt < 2; mt++) mma16816(acc[mt][nt], Ah[mt], bh.x, bh.y);
            #pragma unroll
            for (int mt = 0; mt < 2; mt++) mma16816(acc[mt][nt], Ar[mt], bh.x, bh.y);
            #pragma unroll
            for (int mt = 0; mt < 2; mt++) mma16816(acc[mt][nt], Ah[mt], br.x, br.y);
        }
        __syncthreads();
        if (it + 2 < 16) {
            uint32_t dbase = sb + SB_B + (it & 1) * 16384;
            #pragma unroll
            for (int split = 0; split < 2; split++) {
                const char* src = gb + (size_t)((it + 2) * 2 + split) * 32768 + ct * 8192;
                uint32_t d = dbase + split * 8192;
                cpasync16(d + tid * 32, src + tid * 32);
                cpasync16(d + tid * 32 + 16, src + tid * 32 + 16);
            }
            CP_COMMIT();
        }
    }

    // ---- epilogue: per-row argmin, packed atomicMin ----
    const float* sN = (const float*)(smem + SB_NORM);
    unsigned long long* sred = (unsigned long long*)(smem + SB_RED);
    const int c2 = (lane & 3) * 2;
    #pragma unroll
    for (int mt = 0; mt < 2; mt++) {
        #pragma unroll
        for (int rr = 0; rr < 2; rr++) {
            float bv = 3.4e38f;
            int bn = 0;
            #pragma unroll
            for (int nt = 0; nt < 8; nt++) {
                #pragma unroll
                for (int h = 0; h < 2; h++) {
                    int nl = warpN * 64 + nt * 8 + c2 + h;
                    float sc = fmaf(-2.0f, acc[mt][nt][rr * 2 + h], sN[nl]);
                    if (sc < bv) { bv = sc; bn = nl; }
                }
            }
            unsigned long long key = ((unsigned long long)fkey(bv) << 32)
                                   | (unsigned)(ct * 256 + bn);
            unsigned long long o1 = __shfl_xor_sync(0xffffffffu, key, 1);
            key = key < o1 ? key : o1;
            unsigned long long o2 = __shfl_xor_sync(0xffffffffu, key, 2);
            key = key < o2 ? key : o2;
            if ((lane & 3) == 0) {
                int mrow = warpM * 32 + mt * 16 + rr * 8 + (lane >> 2);
                sred[mrow * 4 + warpN] = key;
            }
        }
    }
    __syncthreads();
    if (tid < 64) {
        unsigned long long k0 = sred[tid * 4 + 0];
        unsigned long long k1 = sred[tid * 4 + 1];
        unsigned long long k2 = sred[tid * 4 + 2];
        unsigned long long k3 = sred[tid * 4 + 3];
        k0 = k0 < k1 ? k0 : k1;
        k2 = k2 < k3 ? k2 : k3;
        k0 = k0 < k2 ? k0 : k2;
        atomicMin(&g_best[n0 + tid], k0);
    }
}

// ---------------------------------------------------------------------------
__global__ void stats_kernel(float* __restrict__ out_idx) {
    int n = blockIdx.x * 256 + threadIdx.x;
    unsigned long long k = g_best[n];
    uint32_t fb = (uint32_t)(k >> 32);
    uint32_t su = (fb & 0x80000000u) ? (fb ^ 0x80000000u) : ~fb;
    float score = __uint_as_float(su);
    int idx = (int)(k & 0xFFFFFFFFu);
    g_idx[n] = idx;
    out_idx[n] = (float)idx;
    atomicAdd(&g_refcount[idx], 1.0f);

    float v = score;
    #pragma unroll
    for (int o = 16; o > 0; o >>= 1) v += __shfl_down_sync(0xffffffffu, v, o);
    __shared__ float ws[8];
    if ((threadIdx.x & 31) == 0) ws[threadIdx.x >> 5] = v;
    __syncthreads();
    if (threadIdx.x == 0) {
        float s = 0.0f;
        #pragma unroll
        for (int w = 0; w < 8; w++) s += ws[w];
        atomicAdd(&g_minsum, s);
    }
}

__global__ void dwx_kernel(const float* __restrict__ x) {
    int n = blockIdx.x * 256 + threadIdx.x;
    int b = n >> 12;
    int hw = n & 4095;
    int idx = g_idx[n];
    const float* xb = x + (size_t)b * DEMB * HWSZ + hw;
    float* dwp = g_dw + idx;
    float s = 0.0f;
    #pragma unroll 4
    for (int d = 0; d < DEMB; d++) {
        float v = xb[(size_t)d * HWSZ];
        atomicAdd(&dwp[d * KEMB], v);
        s = fmaf(v, v, s);
    }
    #pragma unroll
    for (int o = 16; o > 0; o >>= 1) s += __shfl_down_sync(0xffffffffu, s, o);
    __shared__ float ws[8];
    if ((threadIdx.x & 31) == 0) ws[threadIdx.x >> 5] = s;
    __syncthreads();
    if (threadIdx.x == 0) {
        float t = 0.0f;
        #pragma unroll
        for (int w = 0; w < 8; w++) t += ws[w];
        atomicAdd(&g_xsq, t);
    }
}

__global__ void cluster_kernel(const float* __restrict__ cs_in,
                               float* __restrict__ out_ncs,
                               float* __restrict__ out_loss) {
    int k = threadIdx.x;  // 1024 threads
    float ncs = cs_in[k] * 0.9f + 0.1f * g_refcount[k];
    out_ncs[k] = ncs;
    float v = ncs;
    #pragma unroll
    for (int o = 16; o > 0; o >>= 1) v += __shfl_down_sync(0xffffffffu, v, o);
    __shared__ float ws[32];
    if ((k & 31) == 0) ws[k >> 5] = v;
    __syncthreads();
    __shared__ float s_n;
    if (k < 32) {
        float t = ws[k];
        #pragma unroll
        for (int o = 16; o > 0; o >>= 1) t += __shfl_down_sync(0xffffffffu, t, o);
        if (k == 0) s_n = t;
    }
    __syncthreads();
    float n = s_n;
    g_smooth[k] = n * (ncs + 1e-5f) / (n + ncs * 1e-5f);
    if (k == 0)
        out_loss[0] = 0.25f * (g_minsum + g_xsq) / 33554432.0f;
}

__global__ void ema_kernel(const float* __restrict__ ema_in,
                           float* __restrict__ out_nee,
                           float* __restrict__ out_ne) {
    int i = blockIdx.x * blockDim.x + threadIdx.x;  // 262144
    float nee = ema_in[i] * 0.9f + 0.1f * g_dw[i];
    out_nee[i] = nee;
    out_ne[i] = nee / g_smooth[i & 1023];
}

__global__ void quant_kernel(float* __restrict__ out) {
    int n = blockIdx.x * 256 + threadIdx.x;
    int b = n >> 12;
    int hw = n & 4095;
    int idx = g_idx[n];
    const float4* ev = (const float4*)(g_embT + (size_t)idx * 256);
    float* ob = out + (size_t)b * DEMB * HWSZ + hw;
    #pragma unroll 8
    for (int c4 = 0; c4 < 64; c4++) {
        float4 v = __ldg(&ev[c4]);
        ob[(size_t)(4 * c4 + 0) * HWSZ] = v.x;
        ob[(size_t)(4 * c4 + 1) * HWSZ] = v.y;
        ob[(size_t)(4 * c4 + 2) * HWSZ] = v.z;
        ob[(size_t)(4 * c4 + 3) * HWSZ] = v.w;
    }
}

// ---------------------------------------------------------------------------
extern "C" void kernel_launch(void* const* d_in, const int* in_sizes, int n_in,
                              void* d_out, int out_size) {
    const float* x     = (const float*)d_in[0];
    const float* embed = (const float*)d_in[1];
    const float* cs    = (const float*)d_in[2];
    const float* ema   = (const float*)d_in[3];
    float* out = (float*)d_out;

    float* out_loss = out + 33554432;
    float* out_idx  = out + 33554433;
    float* out_ne   = out + 33685505;
    float* out_ncs  = out + 33947649;
    float* out_nee  = out + 33948673;

    cudaFuncSetAttribute(argmin_kernel, cudaFuncAttributeMaxDynamicSharedMemorySize, SM_TOTAL);

    // launch order chosen so argmin_kernel sits in ncu's capture slot (index 3)
    zero_kernel<<<256, 256>>>();
    norms_kernel<<<4, 256>>>(embed);
    embsplit_kernel<<<512, 256>>>(embed);
    argmin_kernel<<<8192, 256, SM_TOTAL>>>(x);
    embT_kernel<<<1024, 256>>>(embed);
    stats_kernel<<<N_TOK / 256, 256>>>(out_idx);
    dwx_kernel<<<N_TOK / 256, 256>>>(x);
    cluster_kernel<<<1, 1024>>>(cs, out_ncs, out_loss);
    ema_kernel<<<1024, 256>>>(ema, out_nee, out_ne);
    quant_kernel<<<N_TOK / 256, 256>>>(out);
}

// round 10
// speedup vs baseline: 2.0631x; 1.0742x over previous
#include <cuda_runtime.h>
#include <cuda_fp16.h>
#include <cstdint>

#define N_TOK 131072
#define DEMB 256
#define KEMB 1024
#define HWSZ 4096

// ---------------------------------------------------------------------------
// device scratch
// ---------------------------------------------------------------------------
__device__ float g_norms[KEMB];
__device__ unsigned long long g_best[N_TOK];
__device__ float g_refcount[KEMB];
__device__ float g_dw[DEMB * KEMB];
__device__ float g_smooth[KEMB];
__device__ float g_embT[KEMB * DEMB];     // embed transposed [k][d]
__device__ float g_minsum;
__device__ float g_xsq;

// B in mma-fragment layout: [ktile 16][split 2][ntile 128][lane 32][reg 2] u32
__device__ __align__(16) uint32_t g_embB[16 * 2 * 128 * 32 * 2];

// ---------------------------------------------------------------------------
// helpers
// ---------------------------------------------------------------------------
__device__ __forceinline__ uint32_t smem_u32(const void* p) {
    uint32_t a;
    asm("{ .reg .u64 t; cvta.to.shared.u64 t, %1; cvt.u32.u64 %0, t; }" : "=r"(a) : "l"(p));
    return a;
}
__device__ __forceinline__ void sts32(uint32_t addr, uint32_t v) {
    asm volatile("st.shared.b32 [%0], %1;" :: "r"(addr), "r"(v) : "memory");
}
__device__ __forceinline__ uint2 lds64(uint32_t addr) {
    uint2 r;
    asm volatile("ld.shared.v2.u32 {%0, %1}, [%2];" : "=r"(r.x), "=r"(r.y) : "r"(addr));
    return r;
}
__device__ __forceinline__ void ldmx4t(uint32_t* r, uint32_t addr) {
    asm volatile("ldmatrix.sync.aligned.m8n8.x4.trans.shared.b16 {%0,%1,%2,%3}, [%4];"
                 : "=r"(r[0]), "=r"(r[1]), "=r"(r[2]), "=r"(r[3]) : "r"(addr));
}
__device__ __forceinline__ void mma16816(float* c, const uint32_t* a, uint32_t b0, uint32_t b1) {
    asm volatile("mma.sync.aligned.m16n8k16.row.col.f32.f16.f16.f32 "
                 "{%0,%1,%2,%3}, {%4,%5,%6,%7}, {%8,%9}, {%0,%1,%2,%3};"
                 : "+f"(c[0]), "+f"(c[1]), "+f"(c[2]), "+f"(c[3])
                 : "r"(a[0]), "r"(a[1]), "r"(a[2]), "r"(a[3]), "r"(b0), "r"(b1));
}
__device__ __forceinline__ void cpasync16(uint32_t dst, const void* src) {
    asm volatile("cp.async.cg.shared.global [%0], [%1], 16;" :: "r"(dst), "l"(src));
}
#define CP_COMMIT() asm volatile("cp.async.commit_group;" ::: "memory")
#define CP_WAIT(n)  asm volatile("cp.async.wait_group %0;" :: "n"(n) : "memory")

__device__ __forceinline__ uint32_t fkey(float f) {
    uint32_t u = __float_as_uint(f);
    return (u & 0x80000000u) ? ~u : (u | 0x80000000u);
}

// ---------------------------------------------------------------------------
// setup kernels
// ---------------------------------------------------------------------------
__global__ void zero_kernel() {
    int i = blockIdx.x * blockDim.x + threadIdx.x;      // 65536 threads
    #pragma unroll
    for (int j = 0; j < 4; j++) g_dw[i + j * 65536] = 0.0f;
    #pragma unroll
    for (int j = 0; j < 2; j++) g_best[i + j * 65536] = 0xFFFFFFFFFFFFFFFFULL;
    if (i < KEMB) g_refcount[i] = 0.0f;
    if (i == 0) { g_minsum = 0.0f; g_xsq = 0.0f; }
}

__global__ void norms_kernel(const float* __restrict__ embed) {
    int k = blockIdx.x * blockDim.x + threadIdx.x;
    if (k < KEMB) {
        float s = 0.0f;
        #pragma unroll 8
        for (int d = 0; d < DEMB; d++) {
            float v = embed[d * KEMB + k];
            s = fmaf(v, v, s);
        }
        g_norms[k] = s;
    }
}

__global__ void embT_kernel(const float* __restrict__ embed) {
    int t = blockIdx.x * 256 + threadIdx.x;   // 262144
    int k = t >> 8, d = t & 255;
    g_embT[t] = embed[d * KEMB + k];
}

// split embed into fp16 h/r, store in B-fragment layout
__global__ void embsplit_kernel(const float* __restrict__ embed) {
    int t = blockIdx.x * 256 + threadIdx.x;   // 131072 threads
    int n = t & 1023;
    int kp = t >> 10;                          // 0..127  -> k = 2*kp
    int k = 2 * kp;
    float v0 = embed[k * KEMB + n];
    float v1 = embed[(k + 1) * KEMB + n];
    __half2 h2 = __float22half2_rn(make_float2(v0, v1));
    float2 hf = __half22float2(h2);
    __half2 r2 = __float22half2_rn(make_float2(v0 - hf.x, v1 - hf.y));
    uint32_t hv = *reinterpret_cast<uint32_t*>(&h2);
    uint32_t rv = *reinterpret_cast<uint32_t*>(&r2);

    int ktile = kp >> 3;
    int lane = (n & 7) * 4 + (kp & 3);
    int reg = (kp >> 2) & 1;
    int ntile = n >> 3;
    uint32_t off = (((uint32_t)(ktile * 2 + 0) * 128 + ntile) * 32 + lane) * 2 + reg;
    g_embB[off] = hv;
    g_embB[off + 128 * 32 * 2] = rv;   // split 1 slot
}

// ---------------------------------------------------------------------------
// HMMA argmin: CTA = 64 tokens x 256 codes, K=256, fp16 2-split x 3 products.
// 2 CTAs/SM. 3-stage cp.async pipeline -> ONE sync per ktile.
// A stored with XOR-16B swizzle (128B rows, no padding).
// ---------------------------------------------------------------------------
#define SA_H 0
#define SA_R 32768
#define SB_B 65536          // 3 stages x 16384 = 49152
#define SM_TOTAL 114688     // 112 KB/CTA -> 2 CTAs = 224 KB

__global__ __launch_bounds__(256, 2) void argmin_kernel(const float* __restrict__ x) {
    extern __shared__ __align__(16) char smem[];
    const uint32_t sb = smem_u32(smem);
    const int tid = threadIdx.x;
    const int lane = tid & 31;
    const int wid = tid >> 5;
    const int warpM = wid >> 2;        // 0..1 (32 rows each)
    const int warpN = wid & 3;         // 0..3 (64 codes each)

    const int tt = blockIdx.x >> 2;
    const int ct = blockIdx.x & 3;
    const int n0 = tt * 64;
    const int b = n0 >> 12;
    const int hw0 = n0 & 4095;
    const float* xb = x + (size_t)b * DEMB * HWSZ + hw0;
    const char* gb = (const char*)g_embB;

    // ---- prologue: B tiles 0,1 into stages 0,1 ----
    #pragma unroll
    for (int c = 0; c < 2; c++) {
        uint32_t dbase = sb + SB_B + c * 16384;
        #pragma unroll
        for (int split = 0; split < 2; split++) {
            const char* src = gb + (size_t)(c * 2 + split) * 32768 + ct * 8192;
            uint32_t d = dbase + split * 8192;
            cpasync16(d + tid * 32, src + tid * 32);
            cpasync16(d + tid * 32 + 16, src + tid * 32 + 16);
        }
        CP_COMMIT();
    }

    // ---- build A splits in smem [k][m], swizzled 128B rows ----
    {
        const uint32_t m4 = (tid & 31) * 4;    // byte col within row
        const int dsel = tid >> 5;
        #pragma unroll 4
        for (int it = 0; it < 32; it++) {
            int d = it * 8 + dsel;
            float2 v = *(const float2*)(xb + (size_t)d * HWSZ + (tid & 31) * 2);
            __half2 h2 = __float22half2_rn(v);
            float2 hf = __half22float2(h2);
            __half2 r2 = __float22half2_rn(make_float2(v.x - hf.x, v.y - hf.y));
            uint32_t aH = sb + SA_H + d * 128 + (m4 ^ (((uint32_t)d & 7) << 4));
            sts32(aH, *reinterpret_cast<uint32_t*>(&h2));
            sts32(aH + SA_R, *reinterpret_cast<uint32_t*>(&r2));
        }
    }

    // ---- mma mainloop: 16 ktiles, 3-stage, one sync each ----
    float acc[2][8][4];
    #pragma unroll
    for (int mt = 0; mt < 2; mt++)
        #pragma unroll
        for (int nt = 0; nt < 8; nt++)
            #pragma unroll
            for (int r = 0; r < 4; r++) acc[mt][nt][r] = 0.0f;

    const int krow = (lane & 7) + ((lane >> 4) << 3);
    const int mcol = ((lane >> 3) & 1) << 3;
    const uint32_t asw = ((uint32_t)lane & 7) << 4;   // row&7 == lane&7 for all ktiles

    for (int it = 0; it < 16; it++) {
        if (it < 15) { CP_WAIT(1); } else { CP_WAIT(0); }
        __syncthreads();
        const uint32_t bufB = sb + SB_B + (it % 3) * 16384;

        uint32_t Ah[2][4], Ar[2][4];
        #pragma unroll
        for (int mt = 0; mt < 2; mt++) {
            uint32_t colb = (uint32_t)(warpM * 32 + mt * 16 + mcol) * 2;
            uint32_t addr = sb + SA_H + (it * 16 + krow) * 128 + (colb ^ asw);
            ldmx4t(Ah[mt], addr);
            ldmx4t(Ar[mt], addr + SA_R);
        }
        #pragma unroll
        for (int nt = 0; nt < 8; nt++) {
            uint32_t tb = bufB + (warpN * 8 + nt) * 256 + lane * 8;
            uint2 bh = lds64(tb);
            uint2 br = lds64(tb + 8192);
            #pragma unroll
            for (int mt = 0; mt < 2; mt++) mma16816(acc[mt][nt], Ah[mt], bh.x, bh.y);
            #pragma unroll
            for (int mt = 0; mt < 2; mt++) mma16816(acc[mt][nt], Ar[mt], bh.x, bh.y);
            #pragma unroll
            for (int mt = 0; mt < 2; mt++) mma16816(acc[mt][nt], Ah[mt], br.x, br.y);
        }
        if (it + 2 < 16) {
            // stage (it+2)%3 == (it-1)%3; its reads finished before this
            // iteration's top barrier, so overwrite is safe with one sync.
            uint32_t dbase = sb + SB_B + ((it + 2) % 3) * 16384;
            #pragma unroll
            for (int split = 0; split < 2; split++) {
                const char* src = gb + (size_t)((it + 2) * 2 + split) * 32768 + ct * 8192;
                uint32_t d = dbase + split * 8192;
                cpasync16(d + tid * 32, src + tid * 32);
                cpasync16(d + tid * 32 + 16, src + tid * 32 + 16);
            }
            CP_COMMIT();
        }
    }

    // ---- epilogue: norms+sred alias the B region (all B reads are done) ----
    __syncthreads();
    float* sN = (float*)(smem + SB_B);                          // 1 KB
    unsigned long long* sred = (unsigned long long*)(smem + SB_B + 1024);  // 2 KB
    sN[tid] = g_norms[ct * 256 + tid];
    __syncthreads();

    const int c2 = (lane & 3) * 2;
    #pragma unroll
    for (int mt = 0; mt < 2; mt++) {
        #pragma unroll
        for (int rr = 0; rr < 2; rr++) {
            float bv = 3.4e38f;
            int bn = 0;
            #pragma unroll
            for (int nt = 0; nt < 8; nt++) {
                #pragma unroll
                for (int h = 0; h < 2; h++) {
                    int nl = warpN * 64 + nt * 8 + c2 + h;
                    float sc = fmaf(-2.0f, acc[mt][nt][rr * 2 + h], sN[nl]);
                    if (sc < bv) { bv = sc; bn = nl; }
                }
            }
            unsigned long long key = ((unsigned long long)fkey(bv) << 32)
                                   | (unsigned)(ct * 256 + bn);
            unsigned long long o1 = __shfl_xor_sync(0xffffffffu, key, 1);
            key = key < o1 ? key : o1;
            unsigned long long o2 = __shfl_xor_sync(0xffffffffu, key, 2);
            key = key < o2 ? key : o2;
            if ((lane & 3) == 0) {
                int mrow = warpM * 32 + mt * 16 + rr * 8 + (lane >> 2);
                sred[mrow * 4 + warpN] = key;
            }
        }
    }
    __syncthreads();
    if (tid < 64) {
        unsigned long long k0 = sred[tid * 4 + 0];
        unsigned long long k1 = sred[tid * 4 + 1];
        unsigned long long k2 = sred[tid * 4 + 2];
        unsigned long long k3 = sred[tid * 4 + 3];
        k0 = k0 < k1 ? k0 : k1;
        k2 = k2 < k3 ? k2 : k3;
        k0 = k0 < k2 ? k0 : k2;
        atomicMin(&g_best[n0 + tid], k0);
    }
}

// ---------------------------------------------------------------------------
// finish: decode g_best -> idx/score; idx out, refcount, minsum;
// read x once (xsq + dw scatter); write quantized out. (stats+dwx+quant fused)
// ---------------------------------------------------------------------------
__global__ void finish_kernel(const float* __restrict__ x,
                              float* __restrict__ out,
                              float* __restrict__ out_idx) {
    int n = blockIdx.x * 256 + threadIdx.x;
    int b = n >> 12;
    int hw = n & 4095;
    unsigned long long k = g_best[n];
    uint32_t fb = (uint32_t)(k >> 32);
    uint32_t su = (fb & 0x80000000u) ? (fb ^ 0x80000000u) : ~fb;
    float score = __uint_as_float(su);
    int idx = (int)(k & 0xFFFFFFFFu);
    out_idx[n] = (float)idx;
    atomicAdd(&g_refcount[idx], 1.0f);

    const float* xb = x + (size_t)b * DEMB * HWSZ + hw;
    float* ob = out + (size_t)b * DEMB * HWSZ + hw;
    const float4* ev = (const float4*)(g_embT + (size_t)idx * 256);
    float* dwp = g_dw + idx;
    float s = 0.0f;
    #pragma unroll 4
    for (int c4 = 0; c4 < 64; c4++) {
        float4 e = __ldg(&ev[c4]);
        float v0 = xb[(size_t)(4 * c4 + 0) * HWSZ];
        float v1 = xb[(size_t)(4 * c4 + 1) * HWSZ];
        float v2 = xb[(size_t)(4 * c4 + 2) * HWSZ];
        float v3 = xb[(size_t)(4 * c4 + 3) * HWSZ];
        atomicAdd(&dwp[(4 * c4 + 0) * KEMB], v0);
        atomicAdd(&dwp[(4 * c4 + 1) * KEMB], v1);
        atomicAdd(&dwp[(4 * c4 + 2) * KEMB], v2);
        atomicAdd(&dwp[(4 * c4 + 3) * KEMB], v3);
        s = fmaf(v0, v0, s); s = fmaf(v1, v1, s);
        s = fmaf(v2, v2, s); s = fmaf(v3, v3, s);
        ob[(size_t)(4 * c4 + 0) * HWSZ] = e.x;
        ob[(size_t)(4 * c4 + 1) * HWSZ] = e.y;
        ob[(size_t)(4 * c4 + 2) * HWSZ] = e.z;
        ob[(size_t)(4 * c4 + 3) * HWSZ] = e.w;
    }

    float v = s;
    float m = score;
    #pragma unroll
    for (int o = 16; o > 0; o >>= 1) {
        v += __shfl_down_sync(0xffffffffu, v, o);
        m += __shfl_down_sync(0xffffffffu, m, o);
    }
    __shared__ float ws[8], wm[8];
    if ((threadIdx.x & 31) == 0) { ws[threadIdx.x >> 5] = v; wm[threadIdx.x >> 5] = m; }
    __syncthreads();
    if (threadIdx.x == 0) {
        float t = 0.0f, u = 0.0f;
        #pragma unroll
        for (int w = 0; w < 8; w++) { t += ws[w]; u += wm[w]; }
        atomicAdd(&g_xsq, t);
        atomicAdd(&g_minsum, u);
    }
}

__global__ void cluster_kernel(const float* __restrict__ cs_in,
                               float* __restrict__ out_ncs,
                               float* __restrict__ out_loss) {
    int k = threadIdx.x;  // 1024 threads
    float ncs = cs_in[k] * 0.9f + 0.1f * g_refcount[k];
    out_ncs[k] = ncs;
    float v = ncs;
    #pragma unroll
    for (int o = 16; o > 0; o >>= 1) v += __shfl_down_sync(0xffffffffu, v, o);
    __shared__ float ws[32];
    if ((k & 31) == 0) ws[k >> 5] = v;
    __syncthreads();
    __shared__ float s_n;
    if (k < 32) {
        float t = ws[k];
        #pragma unroll
        for (int o = 16; o > 0; o >>= 1) t += __shfl_down_sync(0xffffffffu, t, o);
        if (k == 0) s_n = t;
    }
    __syncthreads();
    float n = s_n;
    g_smooth[k] = n * (ncs + 1e-5f) / (n + ncs * 1e-5f);
    if (k == 0)
        out_loss[0] = 0.25f * (g_minsum + g_xsq) / 33554432.0f;
}

__global__ void ema_kernel(const float* __restrict__ ema_in,
                           float* __restrict__ out_nee,
                           float* __restrict__ out_ne) {
    int i = blockIdx.x * blockDim.x + threadIdx.x;  // 262144
    float nee = ema_in[i] * 0.9f + 0.1f * g_dw[i];
    out_nee[i] = nee;
    out_ne[i] = nee / g_smooth[i & 1023];
}

// ---------------------------------------------------------------------------
extern "C" void kernel_launch(void* const* d_in, const int* in_sizes, int n_in,
                              void* d_out, int out_size) {
    const float* x     = (const float*)d_in[0];
    const float* embed = (const float*)d_in[1];
    const float* cs    = (const float*)d_in[2];
    const float* ema   = (const float*)d_in[3];
    float* out = (float*)d_out;

    float* out_loss = out + 33554432;
    float* out_idx  = out + 33554433;
    float* out_ne   = out + 33685505;
    float* out_ncs  = out + 33947649;
    float* out_nee  = out + 33948673;

    cudaFuncSetAttribute(argmin_kernel, cudaFuncAttributeMaxDynamicSharedMemorySize, SM_TOTAL);

    // launch order keeps argmin_kernel in ncu's capture slot (index 3)
    zero_kernel<<<256, 256>>>();
    norms_kernel<<<4, 256>>>(embed);
    embsplit_kernel<<<512, 256>>>(embed);
    argmin_kernel<<<8192, 256, SM_TOTAL>>>(x);
    embT_kernel<<<1024, 256>>>(embed);
    finish_kernel<<<N_TOK / 256, 256>>>(x, out, out_idx);
    cluster_kernel<<<1, 1024>>>(cs, out_ncs, out_loss);
    ema_kernel<<<1024, 256>>>(ema, out_nee, out_ne);
}

// round 15
// speedup vs baseline: 2.0887x; 1.0124x over previous
#include <cuda_runtime.h>
#include <cuda_fp16.h>
#include <cstdint>

#define N_TOK 131072
#define DEMB 256
#define KEMB 1024
#define HWSZ 4096

// ---------------------------------------------------------------------------
// device scratch
// ---------------------------------------------------------------------------
__device__ float g_norms[KEMB];
__device__ unsigned long long g_best[N_TOK];
__device__ float g_refcount[KEMB];
__device__ __align__(16) float g_dw[KEMB * DEMB];   // TRANSPOSED: [k][d]
__device__ float g_smooth[KEMB];
__device__ float g_embT[KEMB * DEMB];     // embed transposed [k][d]
__device__ float g_minsum;
__device__ float g_xsq;

// B in mma-fragment layout: [ktile 16][split 2][ntile 128][lane 32][reg 2] u32
__device__ __align__(16) uint32_t g_embB[16 * 2 * 128 * 32 * 2];

// ---------------------------------------------------------------------------
// helpers
// ---------------------------------------------------------------------------
__device__ __forceinline__ uint32_t smem_u32(const void* p) {
    uint32_t a;
    asm("{ .reg .u64 t; cvta.to.shared.u64 t, %1; cvt.u32.u64 %0, t; }" : "=r"(a) : "l"(p));
    return a;
}
__device__ __forceinline__ void sts32(uint32_t addr, uint32_t v) {
    asm volatile("st.shared.b32 [%0], %1;" :: "r"(addr), "r"(v) : "memory");
}
__device__ __forceinline__ uint2 lds64(uint32_t addr) {
    uint2 r;
    asm volatile("ld.shared.v2.u32 {%0, %1}, [%2];" : "=r"(r.x), "=r"(r.y) : "r"(addr));
    return r;
}
__device__ __forceinline__ void ldmx4t(uint32_t* r, uint32_t addr) {
    asm volatile("ldmatrix.sync.aligned.m8n8.x4.trans.shared.b16 {%0,%1,%2,%3}, [%4];"
                 : "=r"(r[0]), "=r"(r[1]), "=r"(r[2]), "=r"(r[3]) : "r"(addr));
}
__device__ __forceinline__ void mma16816(float* c, const uint32_t* a, uint32_t b0, uint32_t b1) {
    asm volatile("mma.sync.aligned.m16n8k16.row.col.f32.f16.f16.f32 "
                 "{%0,%1,%2,%3}, {%4,%5,%6,%7}, {%8,%9}, {%0,%1,%2,%3};"
                 : "+f"(c[0]), "+f"(c[1]), "+f"(c[2]), "+f"(c[3])
                 : "r"(a[0]), "r"(a[1]), "r"(a[2]), "r"(a[3]), "r"(b0), "r"(b1));
}
__device__ __forceinline__ void cpasync16(uint32_t dst, const void* src) {
    asm volatile("cp.async.cg.shared.global [%0], [%1], 16;" :: "r"(dst), "l"(src));
}
#define CP_COMMIT() asm volatile("cp.async.commit_group;" ::: "memory")
#define CP_WAIT(n)  asm volatile("cp.async.wait_group %0;" :: "n"(n) : "memory")

__device__ __forceinline__ uint32_t fkey(float f) {
    uint32_t u = __float_as_uint(f);
    return (u & 0x80000000u) ? ~u : (u | 0x80000000u);
}

// ---------------------------------------------------------------------------
// setup kernels
// ---------------------------------------------------------------------------
__global__ void zero_kernel() {
    int i = blockIdx.x * blockDim.x + threadIdx.x;      // 65536 threads
    #pragma unroll
    for (int j = 0; j < 4; j++) g_dw[i + j * 65536] = 0.0f;
    #pragma unroll
    for (int j = 0; j < 2; j++) g_best[i + j * 65536] = 0xFFFFFFFFFFFFFFFFULL;
    if (i < KEMB) g_refcount[i] = 0.0f;
    if (i == 0) { g_minsum = 0.0f; g_xsq = 0.0f; }
}

__global__ void norms_kernel(const float* __restrict__ embed) {
    int k = blockIdx.x * blockDim.x + threadIdx.x;
    if (k < KEMB) {
        float s = 0.0f;
        #pragma unroll 8
        for (int d = 0; d < DEMB; d++) {
            float v = embed[d * KEMB + k];
            s = fmaf(v, v, s);
        }
        g_norms[k] = s;
    }
}

__global__ void embT_kernel(const float* __restrict__ embed) {
    int t = blockIdx.x * 256 + threadIdx.x;   // 262144
    int k = t >> 8, d = t & 255;
    g_embT[t] = embed[d * KEMB + k];
}

// split embed into fp16 h/r, store in B-fragment layout
__global__ void embsplit_kernel(const float* __restrict__ embed) {
    int t = blockIdx.x * 256 + threadIdx.x;   // 131072 threads
    int n = t & 1023;
    int kp = t >> 10;                          // 0..127  -> k = 2*kp
    int k = 2 * kp;
    float v0 = embed[k * KEMB + n];
    float v1 = embed[(k + 1) * KEMB + n];
    __half2 h2 = __float22half2_rn(make_float2(v0, v1));
    float2 hf = __half22float2(h2);
    __half2 r2 = __float22half2_rn(make_float2(v0 - hf.x, v1 - hf.y));
    uint32_t hv = *reinterpret_cast<uint32_t*>(&h2);
    uint32_t rv = *reinterpret_cast<uint32_t*>(&r2);

    int ktile = kp >> 3;
    int lane = (n & 7) * 4 + (kp & 3);
    int reg = (kp >> 2) & 1;
    int ntile = n >> 3;
    uint32_t off = (((uint32_t)(ktile * 2 + 0) * 128 + ntile) * 32 + lane) * 2 + reg;
    g_embB[off] = hv;
    g_embB[off + 128 * 32 * 2] = rv;   // split 1 slot
}

// ---------------------------------------------------------------------------
// HMMA argmin: CTA = 64 tokens x 256 codes, K=256, fp16 2-split x 3 products.
// 2 CTAs/SM. 3-stage cp.async pipeline -> ONE sync per ktile.
// A stored with XOR-16B swizzle (128B rows, no padding).
// ---------------------------------------------------------------------------
#define SA_H 0
#define SA_R 32768
#define SB_B 65536          // 3 stages x 16384 = 49152
#define SM_TOTAL 114688     // 112 KB/CTA -> 2 CTAs = 224 KB

__global__ __launch_bounds__(256, 2) void argmin_kernel(const float* __restrict__ x) {
    extern __shared__ __align__(16) char smem[];
    const uint32_t sb = smem_u32(smem);
    const int tid = threadIdx.x;
    const int lane = tid & 31;
    const int wid = tid >> 5;
    const int warpM = wid >> 2;        // 0..1 (32 rows each)
    const int warpN = wid & 3;         // 0..3 (64 codes each)

    const int tt = blockIdx.x >> 2;
    const int ct = blockIdx.x & 3;
    const int n0 = tt * 64;
    const int b = n0 >> 12;
    const int hw0 = n0 & 4095;
    const float* xb = x + (size_t)b * DEMB * HWSZ + hw0;
    const char* gb = (const char*)g_embB;

    // ---- prologue: B tiles 0,1 into stages 0,1 ----
    #pragma unroll
    for (int c = 0; c < 2; c++) {
        uint32_t dbase = sb + SB_B + c * 16384;
        #pragma unroll
        for (int split = 0; split < 2; split++) {
            const char* src = gb + (size_t)(c * 2 + split) * 32768 + ct * 8192;
            uint32_t d = dbase + split * 8192;
            cpasync16(d + tid * 32, src + tid * 32);
            cpasync16(d + tid * 32 + 16, src + tid * 32 + 16);
        }
        CP_COMMIT();
    }

    // ---- build A splits in smem [k][m], swizzled 128B rows ----
    {
        const uint32_t m4 = (tid & 31) * 4;    // byte col within row
        const int dsel = tid >> 5;
        #pragma unroll 4
        for (int it = 0; it < 32; it++) {
            int d = it * 8 + dsel;
            float2 v = *(const float2*)(xb + (size_t)d * HWSZ + (tid & 31) * 2);
            __half2 h2 = __float22half2_rn(v);
            float2 hf = __half22float2(h2);
            __half2 r2 = __float22half2_rn(make_float2(v.x - hf.x, v.y - hf.y));
            uint32_t aH = sb + SA_H + d * 128 + (m4 ^ (((uint32_t)d & 7) << 4));
            sts32(aH, *reinterpret_cast<uint32_t*>(&h2));
            sts32(aH + SA_R, *reinterpret_cast<uint32_t*>(&r2));
        }
    }

    // ---- mma mainloop: 16 ktiles, 3-stage, one sync each ----
    float acc[2][8][4];
    #pragma unroll
    for (int mt = 0; mt < 2; mt++)
        #pragma unroll
        for (int nt = 0; nt < 8; nt++)
            #pragma unroll
            for (int r = 0; r < 4; r++) acc[mt][nt][r] = 0.0f;

    const int krow = (lane & 7) + ((lane >> 4) << 3);
    const int mcol = ((lane >> 3) & 1) << 3;
    const uint32_t asw = ((uint32_t)lane & 7) << 4;   // row&7 == lane&7 for all ktiles

    for (int it = 0; it < 16; it++) {
        if (it < 15) { CP_WAIT(1); } else { CP_WAIT(0); }
        __syncthreads();
        const uint32_t bufB = sb + SB_B + (it % 3) * 16384;

        uint32_t Ah[2][4], Ar[2][4];
        #pragma unroll
        for (int mt = 0; mt < 2; mt++) {
            uint32_t colb = (uint32_t)(warpM * 32 + mt * 16 + mcol) * 2;
            uint32_t addr = sb + SA_H + (it * 16 + krow) * 128 + (colb ^ asw);
            ldmx4t(Ah[mt], addr);
            ldmx4t(Ar[mt], addr + SA_R);
        }
        #pragma unroll
        for (int nt = 0; nt < 8; nt++) {
            uint32_t tb = bufB + (warpN * 8 + nt) * 256 + lane * 8;
            uint2 bh = lds64(tb);
            uint2 br = lds64(tb + 8192);
            #pragma unroll
            for (int mt = 0; mt < 2; mt++) mma16816(acc[mt][nt], Ah[mt], bh.x, bh.y);
            #pragma unroll
            for (int mt = 0; mt < 2; mt++) mma16816(acc[mt][nt], Ar[mt], bh.x, bh.y);
            #pragma unroll
            for (int mt = 0; mt < 2; mt++) mma16816(acc[mt][nt], Ah[mt], br.x, br.y);
        }
        if (it + 2 < 16) {
            // stage (it+2)%3 == (it-1)%3; its reads finished before this
            // iteration's top barrier, so overwrite is safe with one sync.
            uint32_t dbase = sb + SB_B + ((it + 2) % 3) * 16384;
            #pragma unroll
            for (int split = 0; split < 2; split++) {
                const char* src = gb + (size_t)((it + 2) * 2 + split) * 32768 + ct * 8192;
                uint32_t d = dbase + split * 8192;
                cpasync16(d + tid * 32, src + tid * 32);
                cpasync16(d + tid * 32 + 16, src + tid * 32 + 16);
            }
            CP_COMMIT();
        }
    }

    // ---- epilogue: norms+sred alias the B region (all B reads are done) ----
    __syncthreads();
    float* sN = (float*)(smem + SB_B);                          // 1 KB
    unsigned long long* sred = (unsigned long long*)(smem + SB_B + 1024);  // 2 KB
    sN[tid] = g_norms[ct * 256 + tid];
    __syncthreads();

    const int c2 = (lane & 3) * 2;
    #pragma unroll
    for (int mt = 0; mt < 2; mt++) {
        #pragma unroll
        for (int rr = 0; rr < 2; rr++) {
            float bv = 3.4e38f;
            int bn = 0;
            #pragma unroll
            for (int nt = 0; nt < 8; nt++) {
                #pragma unroll
                for (int h = 0; h < 2; h++) {
                    int nl = warpN * 64 + nt * 8 + c2 + h;
                    float sc = fmaf(-2.0f, acc[mt][nt][rr * 2 + h], sN[nl]);
                    if (sc < bv) { bv = sc; bn = nl; }
                }
            }
            unsigned long long key = ((unsigned long long)fkey(bv) << 32)
                                   | (unsigned)(ct * 256 + bn);
            unsigned long long o1 = __shfl_xor_sync(0xffffffffu, key, 1);
            key = key < o1 ? key : o1;
            unsigned long long o2 = __shfl_xor_sync(0xffffffffu, key, 2);
            key = key < o2 ? key : o2;
            if ((lane & 3) == 0) {
                int mrow = warpM * 32 + mt * 16 + rr * 8 + (lane >> 2);
                sred[mrow * 4 + warpN] = key;
            }
        }
    }
    __syncthreads();
    if (tid < 64) {
        unsigned long long k0 = sred[tid * 4 + 0];
        unsigned long long k1 = sred[tid * 4 + 1];
        unsigned long long k2 = sred[tid * 4 + 2];
        unsigned long long k3 = sred[tid * 4 + 3];
        k0 = k0 < k1 ? k0 : k1;
        k2 = k2 < k3 ? k2 : k3;
        k0 = k0 < k2 ? k0 : k2;
        atomicMin(&g_best[n0 + tid], k0);
    }
}

// ---------------------------------------------------------------------------
// finish: decode g_best -> idx/score; idx out, refcount, minsum;
// read x once (xsq + dw float4 scatter); write quantized out.
// dw is [k][d] so each token's 256 targets are contiguous -> float4 atomics.
// ---------------------------------------------------------------------------
__global__ void finish_kernel(const float* __restrict__ x,
                              float* __restrict__ out,
                              float* __restrict__ out_idx) {
    int n = blockIdx.x * 256 + threadIdx.x;
    int b = n >> 12;
    int hw = n & 4095;
    unsigned long long k = g_best[n];
    uint32_t fb = (uint32_t)(k >> 32);
    uint32_t su = (fb & 0x80000000u) ? (fb ^ 0x80000000u) : ~fb;
    float score = __uint_as_float(su);
    int idx = (int)(k & 0xFFFFFFFFu);
    out_idx[n] = (float)idx;
    atomicAdd(&g_refcount[idx], 1.0f);

    const float* xb = x + (size_t)b * DEMB * HWSZ + hw;
    float* ob = out + (size_t)b * DEMB * HWSZ + hw;
    const float4* ev = (const float4*)(g_embT + (size_t)idx * 256);
    float4* dwp = (float4*)(g_dw + (size_t)idx * 256);
    float s = 0.0f;
    #pragma unroll 4
    for (int c4 = 0; c4 < 64; c4++) {
        float4 e = __ldg(&ev[c4]);
        float v0 = xb[(size_t)(4 * c4 + 0) * HWSZ];
        float v1 = xb[(size_t)(4 * c4 + 1) * HWSZ];
        float v2 = xb[(size_t)(4 * c4 + 2) * HWSZ];
        float v3 = xb[(size_t)(4 * c4 + 3) * HWSZ];
        atomicAdd(&dwp[c4], make_float4(v0, v1, v2, v3));
        s = fmaf(v0, v0, s); s = fmaf(v1, v1, s);
        s = fmaf(v2, v2, s); s = fmaf(v3, v3, s);
        ob[(size_t)(4 * c4 + 0) * HWSZ] = e.x;
        ob[(size_t)(4 * c4 + 1) * HWSZ] = e.y;
        ob[(size_t)(4 * c4 + 2) * HWSZ] = e.z;
        ob[(size_t)(4 * c4 + 3) * HWSZ] = e.w;
    }

    float v = s;
    float m = score;
    #pragma unroll
    for (int o = 16; o > 0; o >>= 1) {
        v += __shfl_down_sync(0xffffffffu, v, o);
        m += __shfl_down_sync(0xffffffffu, m, o);
    }
    __shared__ float ws[8], wm[8];
    if ((threadIdx.x & 31) == 0) { ws[threadIdx.x >> 5] = v; wm[threadIdx.x >> 5] = m; }
    __syncthreads();
    if (threadIdx.x == 0) {
        float t = 0.0f, u = 0.0f;
        #pragma unroll
        for (int w = 0; w < 8; w++) { t += ws[w]; u += wm[w]; }
        atomicAdd(&g_xsq, t);
        atomicAdd(&g_minsum, u);
    }
}

__global__ void cluster_kernel(const float* __restrict__ cs_in,
                               float* __restrict__ out_ncs,
                               float* __restrict__ out_loss) {
    int k = threadIdx.x;  // 1024 threads
    float ncs = cs_in[k] * 0.9f + 0.1f * g_refcount[k];
    out_ncs[k] = ncs;
    float v = ncs;
    #pragma unroll
    for (int o = 16; o > 0; o >>= 1) v += __shfl_down_sync(0xffffffffu, v, o);
    __shared__ float ws[32];
    if ((k & 31) == 0) ws[k >> 5] = v;
    __syncthreads();
    __shared__ float s_n;
    if (k < 32) {
        float t = ws[k];
        #pragma unroll
        for (int o = 16; o > 0; o >>= 1) t += __shfl_down_sync(0xffffffffu, t, o);
        if (k == 0) s_n = t;
    }
    __syncthreads();
    float n = s_n;
    g_smooth[k] = n * (ncs + 1e-5f) / (n + ncs * 1e-5f);
    if (k == 0)
        out_loss[0] = 0.25f * (g_minsum + g_xsq) / 33554432.0f;
}

__global__ void ema_kernel(const float* __restrict__ ema_in,
                           float* __restrict__ out_nee,
                           float* __restrict__ out_ne) {
    int i = blockIdx.x * blockDim.x + threadIdx.x;  // 262144; i = d*1024 + k
    int d = i >> 10, kk = i & 1023;
    float dwv = g_dw[(size_t)kk * 256 + d];         // transposed gather (L2-resident)
    float nee = ema_in[i] * 0.9f + 0.1f * dwv;
    out_nee[i] = nee;
    out_ne[i] = nee / g_smooth[kk];
}

// ---------------------------------------------------------------------------
extern "C" void kernel_launch(void* const* d_in, const int* in_sizes, int n_in,
                              void* d_out, int out_size) {
    const float* x     = (const float*)d_in[0];
    const float* embed = (const float*)d_in[1];
    const float* cs    = (const float*)d_in[2];
    const float* ema   = (const float*)d_in[3];
    float* out = (float*)d_out;

    float* out_loss = out + 33554432;
    float* out_idx  = out + 33554433;
    float* out_ne   = out + 33685505;
    float* out_ncs  = out + 33947649;
    float* out_nee  = out + 33948673;

    cudaFuncSetAttribute(argmin_kernel, cudaFuncAttributeMaxDynamicSharedMemorySize, SM_TOTAL);

    // launch order keeps argmin_kernel in ncu's capture slot (index 3)
    zero_kernel<<<256, 256>>>();
    norms_kernel<<<4, 256>>>(embed);
    embsplit_kernel<<<512, 256>>>(embed);
    argmin_kernel<<<8192, 256, SM_TOTAL>>>(x);
    embT_kernel<<<1024, 256>>>(embed);
    finish_kernel<<<N_TOK / 256, 256>>>(x, out, out_idx);
    cluster_kernel<<<1, 1024>>>(cs, out_ncs, out_loss);
    ema_kernel<<<1024, 256>>>(ema, out_nee, out_ne);
}

// round 16
// speedup vs baseline: 2.4269x; 1.1619x over previous
#include <cuda_runtime.h>
#include <cuda_fp16.h>
#include <cstdint>

#define N_TOK 131072
#define DEMB 256
#define KEMB 1024
#define HWSZ 4096

// ---------------------------------------------------------------------------
// device scratch
// ---------------------------------------------------------------------------
__device__ float g_norms[KEMB];
__device__ unsigned long long g_best[N_TOK];
__device__ float g_refcount[KEMB];
__device__ __align__(16) float g_dw[KEMB * DEMB];   // TRANSPOSED: [k][d]
__device__ float g_smooth[KEMB];
__device__ float g_embT[KEMB * DEMB];     // embed transposed [k][d]
__device__ float g_minsum;
__device__ float g_xsq;

// B fragments, split-interleaved:
// [ktile 16][ntile 128][lane 32][h0,h1,r0,r1]  (u32 each) = 4 MB
__device__ __align__(16) uint32_t g_embB[16 * 128 * 32 * 4];

// ---------------------------------------------------------------------------
// helpers
// ---------------------------------------------------------------------------
__device__ __forceinline__ uint32_t smem_u32(const void* p) {
    uint32_t a;
    asm("{ .reg .u64 t; cvta.to.shared.u64 t, %1; cvt.u32.u64 %0, t; }" : "=r"(a) : "l"(p));
    return a;
}
__device__ __forceinline__ void sts32(uint32_t addr, uint32_t v) {
    asm volatile("st.shared.b32 [%0], %1;" :: "r"(addr), "r"(v) : "memory");
}
__device__ __forceinline__ uint4 lds128(uint32_t addr) {
    uint4 r;
    asm volatile("ld.shared.v4.u32 {%0, %1, %2, %3}, [%4];"
                 : "=r"(r.x), "=r"(r.y), "=r"(r.z), "=r"(r.w) : "r"(addr));
    return r;
}
__device__ __forceinline__ void ldmx4t(uint32_t* r, uint32_t addr) {
    asm volatile("ldmatrix.sync.aligned.m8n8.x4.trans.shared.b16 {%0,%1,%2,%3}, [%4];"
                 : "=r"(r[0]), "=r"(r[1]), "=r"(r[2]), "=r"(r[3]) : "r"(addr));
}
__device__ __forceinline__ void mma16816(float* c, const uint32_t* a, uint32_t b0, uint32_t b1) {
    asm volatile("mma.sync.aligned.m16n8k16.row.col.f32.f16.f16.f32 "
                 "{%0,%1,%2,%3}, {%4,%5,%6,%7}, {%8,%9}, {%0,%1,%2,%3};"
                 : "+f"(c[0]), "+f"(c[1]), "+f"(c[2]), "+f"(c[3])
                 : "r"(a[0]), "r"(a[1]), "r"(a[2]), "r"(a[3]), "r"(b0), "r"(b1));
}
__device__ __forceinline__ void cpasync16(uint32_t dst, const void* src) {
    asm volatile("cp.async.cg.shared.global [%0], [%1], 16;" :: "r"(dst), "l"(src));
}
#define CP_COMMIT() asm volatile("cp.async.commit_group;" ::: "memory")
#define CP_WAIT(n)  asm volatile("cp.async.wait_group %0;" :: "n"(n) : "memory")

__device__ __forceinline__ uint32_t fkey(float f) {
    uint32_t u = __float_as_uint(f);
    return (u & 0x80000000u) ? ~u : (u | 0x80000000u);
}

// ---------------------------------------------------------------------------
// setup kernels
// ---------------------------------------------------------------------------
__global__ void zero_kernel() {
    int i = blockIdx.x * blockDim.x + threadIdx.x;      // 65536 threads
    #pragma unroll
    for (int j = 0; j < 4; j++) g_dw[i + j * 65536] = 0.0f;
    #pragma unroll
    for (int j = 0; j < 2; j++) g_best[i + j * 65536] = 0xFFFFFFFFFFFFFFFFULL;
    if (i < KEMB) g_refcount[i] = 0.0f;
    if (i == 0) { g_minsum = 0.0f; g_xsq = 0.0f; }
}

__global__ void norms_kernel(const float* __restrict__ embed) {
    int k = blockIdx.x * blockDim.x + threadIdx.x;
    if (k < KEMB) {
        float s = 0.0f;
        #pragma unroll 8
        for (int d = 0; d < DEMB; d++) {
            float v = embed[d * KEMB + k];
            s = fmaf(v, v, s);
        }
        g_norms[k] = s;
    }
}

__global__ void embT_kernel(const float* __restrict__ embed) {
    int t = blockIdx.x * 256 + threadIdx.x;   // 262144
    int k = t >> 8, d = t & 255;
    g_embT[t] = embed[d * KEMB + k];
}

// split embed into fp16 h/r, store split-interleaved fragment layout
__global__ void embsplit_kernel(const float* __restrict__ embed) {
    int t = blockIdx.x * 256 + threadIdx.x;   // 131072 threads
    int n = t & 1023;
    int kp = t >> 10;                          // 0..127  -> k = 2*kp
    int k = 2 * kp;
    float v0 = embed[k * KEMB + n];
    float v1 = embed[(k + 1) * KEMB + n];
    __half2 h2 = __float22half2_rn(make_float2(v0, v1));
    float2 hf = __half22float2(h2);
    __half2 r2 = __float22half2_rn(make_float2(v0 - hf.x, v1 - hf.y));
    uint32_t hv = *reinterpret_cast<uint32_t*>(&h2);
    uint32_t rv = *reinterpret_cast<uint32_t*>(&r2);

    int ktile = kp >> 3;
    int lane = (n & 7) * 4 + (kp & 3);
    int reg = (kp >> 2) & 1;
    int ntile = n >> 3;
    // [ktile][ntile][lane][split*2 + reg]
    uint32_t off = (((uint32_t)ktile * 128 + ntile) * 32 + lane) * 4 + reg;
    g_embB[off] = hv;         // split 0
    g_embB[off + 2] = rv;     // split 1
}

// ---------------------------------------------------------------------------
// HMMA argmin: CTA = 64 tokens x 256 codes, K=256, fp16 2-split x 3 products.
// 2 CTAs/SM. 3-stage cp.async pipeline, one sync per ktile.
// B splits interleaved -> one lds128 feeds all 3 products for an nt tile.
// ---------------------------------------------------------------------------
#define SA_H 0
#define SA_R 32768
#define SB_B 65536          // 3 stages x 16384 = 49152
#define SM_TOTAL 114688     // 112 KB/CTA -> 2 CTAs = 224 KB

__global__ __launch_bounds__(256, 2) void argmin_kernel(const float* __restrict__ x) {
    extern __shared__ __align__(16) char smem[];
    const uint32_t sb = smem_u32(smem);
    const int tid = threadIdx.x;
    const int lane = tid & 31;
    const int wid = tid >> 5;
    const int warpM = wid >> 2;        // 0..1 (32 rows each)
    const int warpN = wid & 3;         // 0..3 (64 codes each)

    const int tt = blockIdx.x >> 2;
    const int ct = blockIdx.x & 3;
    const int n0 = tt * 64;
    const int b = n0 >> 12;
    const int hw0 = n0 & 4095;
    const float* xb = x + (size_t)b * DEMB * HWSZ + hw0;
    const char* gb = (const char*)g_embB;

    // ---- prologue: B ktiles 0,1 into stages 0,1 (16 KB contiguous each) ----
    #pragma unroll
    for (int c = 0; c < 2; c++) {
        const char* src = gb + (size_t)c * 65536 + ct * 16384;
        uint32_t d = sb + SB_B + c * 16384;
        #pragma unroll
        for (int j = 0; j < 4; j++)
            cpasync16(d + tid * 16 + j * 4096, src + tid * 16 + j * 4096);
        CP_COMMIT();
    }

    // ---- build A splits in smem [k][m], swizzled 128B rows ----
    {
        const uint32_t m4 = (tid & 31) * 4;    // byte col within row
        const int dsel = tid >> 5;
        #pragma unroll 4
        for (int it = 0; it < 32; it++) {
            int d = it * 8 + dsel;
            float2 v = *(const float2*)(xb + (size_t)d * HWSZ + (tid & 31) * 2);
            __half2 h2 = __float22half2_rn(v);
            float2 hf = __half22float2(h2);
            __half2 r2 = __float22half2_rn(make_float2(v.x - hf.x, v.y - hf.y));
            uint32_t aH = sb + SA_H + d * 128 + (m4 ^ (((uint32_t)d & 7) << 4));
            sts32(aH, *reinterpret_cast<uint32_t*>(&h2));
            sts32(aH + SA_R, *reinterpret_cast<uint32_t*>(&r2));
        }
    }

    // ---- mma mainloop: 16 ktiles, 3-stage, one sync each ----
    float acc[2][8][4];
    #pragma unroll
    for (int mt = 0; mt < 2; mt++)
        #pragma unroll
        for (int nt = 0; nt < 8; nt++)
            #pragma unroll
            for (int r = 0; r < 4; r++) acc[mt][nt][r] = 0.0f;

    const int krow = (lane & 7) + ((lane >> 4) << 3);
    const int mcol = ((lane >> 3) & 1) << 3;
    const uint32_t asw = ((uint32_t)lane & 7) << 4;   // row&7 == lane&7 for all ktiles

    for (int it = 0; it < 16; it++) {
        if (it < 15) { CP_WAIT(1); } else { CP_WAIT(0); }
        __syncthreads();
        const uint32_t bufB = sb + SB_B + (it % 3) * 16384;

        uint32_t Ah[2][4], Ar[2][4];
        #pragma unroll
        for (int mt = 0; mt < 2; mt++) {
            uint32_t colb = (uint32_t)(warpM * 32 + mt * 16 + mcol) * 2;
            uint32_t addr = sb + SA_H + (it * 16 + krow) * 128 + (colb ^ asw);
            ldmx4t(Ah[mt], addr);
            ldmx4t(Ar[mt], addr + SA_R);
        }
        #pragma unroll
        for (int nt = 0; nt < 8; nt++) {
            uint32_t tb = bufB + (warpN * 8 + nt) * 512 + lane * 16;
            uint4 bq = lds128(tb);       // {bh0, bh1, br0, br1}
            #pragma unroll
            for (int mt = 0; mt < 2; mt++) mma16816(acc[mt][nt], Ah[mt], bq.x, bq.y);
            #pragma unroll
            for (int mt = 0; mt < 2; mt++) mma16816(acc[mt][nt], Ar[mt], bq.x, bq.y);
            #pragma unroll
            for (int mt = 0; mt < 2; mt++) mma16816(acc[mt][nt], Ah[mt], bq.z, bq.w);
        }
        if (it + 2 < 16) {
            // stage (it+2)%3 == (it-1)%3; its reads finished before this
            // iteration's top barrier, so overwrite is safe with one sync.
            const char* src = gb + (size_t)(it + 2) * 65536 + ct * 16384;
            uint32_t d = sb + SB_B + ((it + 2) % 3) * 16384;
            #pragma unroll
            for (int j = 0; j < 4; j++)
                cpasync16(d + tid * 16 + j * 4096, src + tid * 16 + j * 4096);
            CP_COMMIT();
        }
    }

    // ---- epilogue: norms+sred alias the B region (all B reads are done) ----
    __syncthreads();
    float* sN = (float*)(smem + SB_B);                          // 1 KB
    unsigned long long* sred = (unsigned long long*)(smem + SB_B + 1024);  // 2 KB
    sN[tid] = g_norms[ct * 256 + tid];
    __syncthreads();

    const int c2 = (lane & 3) * 2;
    #pragma unroll
    for (int mt = 0; mt < 2; mt++) {
        #pragma unroll
        for (int rr = 0; rr < 2; rr++) {
            float bv = 3.4e38f;
            int bn = 0;
            #pragma unroll
            for (int nt = 0; nt < 8; nt++) {
                #pragma unroll
                for (int h = 0; h < 2; h++) {
                    int nl = warpN * 64 + nt * 8 + c2 + h;
                    float sc = fmaf(-2.0f, acc[mt][nt][rr * 2 + h], sN[nl]);
                    if (sc < bv) { bv = sc; bn = nl; }
                }
            }
            unsigned long long key = ((unsigned long long)fkey(bv) << 32)
                                   | (unsigned)(ct * 256 + bn);
            unsigned long long o1 = __shfl_xor_sync(0xffffffffu, key, 1);
            key = key < o1 ? key : o1;
            unsigned long long o2 = __shfl_xor_sync(0xffffffffu, key, 2);
            key = key < o2 ? key : o2;
            if ((lane & 3) == 0) {
                int mrow = warpM * 32 + mt * 16 + rr * 8 + (lane >> 2);
                sred[mrow * 4 + warpN] = key;
            }
        }
    }
    __syncthreads();
    if (tid < 64) {
        unsigned long long k0 = sred[tid * 4 + 0];
        unsigned long long k1 = sred[tid * 4 + 1];
        unsigned long long k2 = sred[tid * 4 + 2];
        unsigned long long k3 = sred[tid * 4 + 3];
        k0 = k0 < k1 ? k0 : k1;
        k2 = k2 < k3 ? k2 : k3;
        k0 = k0 < k2 ? k0 : k2;
        atomicMin(&g_best[n0 + tid], k0);
    }
}

// ---------------------------------------------------------------------------
// finish: decode g_best -> idx/score; idx out, refcount, minsum;
// read x once (xsq + dw float4 scatter); write quantized out.
// ---------------------------------------------------------------------------
__global__ void finish_kernel(const float* __restrict__ x,
                              float* __restrict__ out,
                              float* __restrict__ out_idx) {
    int n = blockIdx.x * 256 + threadIdx.x;
    int b = n >> 12;
    int hw = n & 4095;
    unsigned long long k = g_best[n];
    uint32_t fb = (uint32_t)(k >> 32);
    uint32_t su = (fb & 0x80000000u) ? (fb ^ 0x80000000u) : ~fb;
    float score = __uint_as_float(su);
    int idx = (int)(k & 0xFFFFFFFFu);
    out_idx[n] = (float)idx;
    atomicAdd(&g_refcount[idx], 1.0f);

    const float* xb = x + (size_t)b * DEMB * HWSZ + hw;
    float* ob = out + (size_t)b * DEMB * HWSZ + hw;
    const float4* ev = (const float4*)(g_embT + (size_t)idx * 256);
    float4* dwp = (float4*)(g_dw + (size_t)idx * 256);
    float s = 0.0f;
    #pragma unroll 4
    for (int c4 = 0; c4 < 64; c4++) {
        float4 e = __ldg(&ev[c4]);
        float v0 = xb[(size_t)(4 * c4 + 0) * HWSZ];
        float v1 = xb[(size_t)(4 * c4 + 1) * HWSZ];
        float v2 = xb[(size_t)(4 * c4 + 2) * HWSZ];
        float v3 = xb[(size_t)(4 * c4 + 3) * HWSZ];
        atomicAdd(&dwp[c4], make_float4(v0, v1, v2, v3));
        s = fmaf(v0, v0, s); s = fmaf(v1, v1, s);
        s = fmaf(v2, v2, s); s = fmaf(v3, v3, s);
        ob[(size_t)(4 * c4 + 0) * HWSZ] = e.x;
        ob[(size_t)(4 * c4 + 1) * HWSZ] = e.y;
        ob[(size_t)(4 * c4 + 2) * HWSZ] = e.z;
        ob[(size_t)(4 * c4 + 3) * HWSZ] = e.w;
    }

    float v = s;
    float m = score;
    #pragma unroll
    for (int o = 16; o > 0; o >>= 1) {
        v += __shfl_down_sync(0xffffffffu, v, o);
        m += __shfl_down_sync(0xffffffffu, m, o);
    }
    __shared__ float ws[8], wm[8];
    if ((threadIdx.x & 31) == 0) { ws[threadIdx.x >> 5] = v; wm[threadIdx.x >> 5] = m; }
    __syncthreads();
    if (threadIdx.x == 0) {
        float t = 0.0f, u = 0.0f;
        #pragma unroll
        for (int w = 0; w < 8; w++) { t += ws[w]; u += wm[w]; }
        atomicAdd(&g_xsq, t);
        atomicAdd(&g_minsum, u);
    }
}

__global__ void cluster_kernel(const float* __restrict__ cs_in,
                               float* __restrict__ out_ncs,
                               float* __restrict__ out_loss) {
    int k = threadIdx.x;  // 1024 threads
    float ncs = cs_in[k] * 0.9f + 0.1f * g_refcount[k];
    out_ncs[k] = ncs;
    float v = ncs;
    #pragma unroll
    for (int o = 16; o > 0; o >>= 1) v += __shfl_down_sync(0xffffffffu, v, o);
    __shared__ float ws[32];
    if ((k & 31) == 0) ws[k >> 5] = v;
    __syncthreads();
    __shared__ float s_n;
    if (k < 32) {
        float t = ws[k];
        #pragma unroll
        for (int o = 16; o > 0; o >>= 1) t += __shfl_down_sync(0xffffffffu, t, o);
        if (k == 0) s_n = t;
    }
    __syncthreads();
    float n = s_n;
    g_smooth[k] = n * (ncs + 1e-5f) / (n + ncs * 1e-5f);
    if (k == 0)
        out_loss[0] = 0.25f * (g_minsum + g_xsq) / 33554432.0f;
}

__global__ void ema_kernel(const float* __restrict__ ema_in,
                           float* __restrict__ out_nee,
                           float* __restrict__ out_ne) {
    int i = blockIdx.x * blockDim.x + threadIdx.x;  // 262144; i = d*1024 + k
    int d = i >> 10, kk = i & 1023;
    float dwv = g_dw[(size_t)kk * 256 + d];         // transposed gather (L2-resident)
    float nee = ema_in[i] * 0.9f + 0.1f * dwv;
    out_nee[i] = nee;
    out_ne[i] = nee / g_smooth[kk];
}

// ---------------------------------------------------------------------------
extern "C" void kernel_launch(void* const* d_in, const int* in_sizes, int n_in,
                              void* d_out, int out_size) {
    const float* x     = (const float*)d_in[0];
    const float* embed = (const float*)d_in[1];
    const float* cs    = (const float*)d_in[2];
    const float* ema   = (const float*)d_in[3];
    float* out = (float*)d_out;

    float* out_loss = out + 33554432;
    float* out_idx  = out + 33554433;
    float* out_ne   = out + 33685505;
    float* out_ncs  = out + 33947649;
    float* out_nee  = out + 33948673;

    cudaFuncSetAttribute(argmin_kernel, cudaFuncAttributeMaxDynamicSharedMemorySize, SM_TOTAL);

    // launch order keeps argmin_kernel in ncu's capture slot (index 3)
    zero_kernel<<<256, 256>>>();
    norms_kernel<<<4, 256>>>(embed);
    embsplit_kernel<<<512, 256>>>(embed);
    argmin_kernel<<<8192, 256, SM_TOTAL>>>(x);
    embT_kernel<<<1024, 256>>>(embed);
    finish_kernel<<<N_TOK / 256, 256>>>(x, out, out_idx);
    cluster_kernel<<<1, 1024>>>(cs, out_ncs, out_loss);
    ema_kernel<<<1024, 256>>>(ema, out_nee, out_ne);
}